// round 3
// baseline (speedup 1.0000x reference)
#include <cuda_runtime.h>

#define N_NODES 100000
#define N_EDGES 1600000
#define IN_DIM  256
#define HID     128
#define OUT_DIM 40

typedef unsigned long long u64;

// ---- scratch ----
__device__ float g_deg[N_NODES];
__device__ float g_isd[N_NODES];
__device__ float g_h1[(size_t)N_NODES * HID];     // h1' = (x@W1)*isd[row]
__device__ float g_agg1[(size_t)N_NODES * HID];   // b1 + sum isd_d*h1'[src]
__device__ float g_h2[(size_t)N_NODES * OUT_DIM]; // h2' = (relu(agg1)@W2)*isd[row]

#define FMA2(d, a, b) asm("fma.rn.f32x2 %0, %1, %2, %3;" : "=l"(d) : "l"(a), "l"(b), "l"(d))
#define F2LL(x) __double_as_longlong(x)

// ---------------------------------------------------------------- degree ----
__global__ void k_zero_deg(int n) {
    int i = blockIdx.x * blockDim.x + threadIdx.x;
    if (i < n) g_deg[i] = 0.f;
}
__global__ void k_count(const int* __restrict__ dst, int e) {
    int i = blockIdx.x * blockDim.x + threadIdx.x;
    if (i < e) atomicAdd(&g_deg[dst[i]], 1.0f);
}
__global__ void k_isd(int n) {
    int i = blockIdx.x * blockDim.x + threadIdx.x;
    if (i < n) {
        float d = g_deg[i];
        g_isd[i] = (d > 0.f) ? rsqrtf(d) : 0.f;
    }
}

// ---------------------------------------------------------------- GEMM1 -----
// h1'[N,128] = (x[N,256] @ W1[256,128]) * isd[row]
// BM=128, BN=64, BK=16, 256 threads, TM=4 (m), TN=8 (n), FFMA2 paired over K:
// each u64 accumulator = (sum over even k, sum over odd k); reduced at the end.
// sA[kk][m] = (x[m][2kk], x[m][2kk+1])   (k-pair transposed, no duplication)
// sB[kk][n] = (W[2kk][n], W[2kk+1][n])   (k-pair interleaved)
__global__ void __launch_bounds__(256, 2)
k_gemm1(const float* __restrict__ x, const float* __restrict__ W, int n) {
    __shared__ float2 sA[2][8][134];  // pad 134 -> conflict-free STS, 16B rows
    __shared__ float2 sB[2][8][64];
    const int tid = threadIdx.x;
    const int tx = tid & 7;          // n-thread: cols 16*g + 2*tx + {0,1}
    const int ty = tid >> 3;         // m-thread: rows {2ty,2ty+1,64+2ty,65+2ty}
    const int m0 = blockIdx.x * 128;
    const int n0 = blockIdx.y * 64;
    const int la_kk = tid & 7, la_m = tid >> 3;
    const int lb_n = tid & 63, lb_kk = tid >> 6;

    u64 acc[4][8];
    #pragma unroll
    for (int p = 0; p < 4; p++)
        #pragma unroll
        for (int q = 0; q < 8; q++) acc[p][q] = 0ULL;

    float2 ra[4], rb[2];

    // prologue: load tile 0 into regs, stage into buf 0
    #pragma unroll
    for (int j = 0; j < 4; j++) {
        int row = m0 + la_m + 32 * j;
        ra[j] = (row < n) ? *(const float2*)&x[(size_t)row * IN_DIM + 2 * la_kk]
                          : make_float2(0.f, 0.f);
    }
    #pragma unroll
    for (int j = 0; j < 2; j++) {
        int kk = lb_kk + 4 * j;
        const float* w = &W[(size_t)(2 * kk) * HID + n0 + lb_n];
        rb[j] = make_float2(w[0], w[HID]);
    }
    #pragma unroll
    for (int j = 0; j < 4; j++) sA[0][la_kk][la_m + 32 * j] = ra[j];
    #pragma unroll
    for (int j = 0; j < 2; j++) sB[0][lb_kk + 4 * j][lb_n] = rb[j];
    __syncthreads();

    #pragma unroll 1
    for (int it = 0; it < 16; it++) {
        int buf = it & 1;
        if (it < 15) {  // stage next tile into regs (hidden behind compute)
            int k0 = (it + 1) * 16;
            #pragma unroll
            for (int j = 0; j < 4; j++) {
                int row = m0 + la_m + 32 * j;
                ra[j] = (row < n) ? *(const float2*)&x[(size_t)row * IN_DIM + k0 + 2 * la_kk]
                                  : make_float2(0.f, 0.f);
            }
            #pragma unroll
            for (int j = 0; j < 2; j++) {
                int kk = lb_kk + 4 * j;
                const float* w = &W[(size_t)(k0 + 2 * kk) * HID + n0 + lb_n];
                rb[j] = make_float2(w[0], w[HID]);
            }
        }
        #pragma unroll
        for (int kk = 0; kk < 8; kk++) {
            double2 aL = *(const double2*)&sA[buf][kk][2 * ty];       // 1-phase
            double2 aH = *(const double2*)&sA[buf][kk][64 + 2 * ty];  // 1-phase
            u64 av[4] = { F2LL(aL.x), F2LL(aL.y), F2LL(aH.x), F2LL(aH.y) };
            u64 bv[8];
            #pragma unroll
            for (int g = 0; g < 4; g++) {
                double2 bg = *(const double2*)&sB[buf][kk][16 * g + 2 * tx];  // 1-phase
                bv[2 * g] = F2LL(bg.x); bv[2 * g + 1] = F2LL(bg.y);
            }
            #pragma unroll
            for (int p = 0; p < 4; p++)
                #pragma unroll
                for (int q = 0; q < 8; q++)
                    FMA2(acc[p][q], av[p], bv[q]);
        }
        if (it < 15) {
            int nb = buf ^ 1;
            #pragma unroll
            for (int j = 0; j < 4; j++) sA[nb][la_kk][la_m + 32 * j] = ra[j];
            #pragma unroll
            for (int j = 0; j < 2; j++) sB[nb][lb_kk + 4 * j][lb_n] = rb[j];
            __syncthreads();
        }
    }

    // epilogue: reduce k-pairs, scale by isd[row]
    #pragma unroll
    for (int p = 0; p < 4; p++) {
        int row = m0 + ((p < 2) ? (2 * ty + p) : (62 + 2 * ty + p));
        if (row < n) {
            float s = g_isd[row];
            #pragma unroll
            for (int g = 0; g < 4; g++) {
                float2 f0 = *(float2*)&acc[p][2 * g];
                float2 f1 = *(float2*)&acc[p][2 * g + 1];
                float2 o = make_float2((f0.x + f0.y) * s, (f1.x + f1.y) * s);
                *(float2*)&g_h1[(size_t)row * HID + n0 + 16 * g + 2 * tx] = o;
            }
        }
    }
}

// ------------------------------------------------------- layer1 edge agg ----
__global__ void k_prefill1(const float* __restrict__ b1, int n) {
    int i = blockIdx.x * blockDim.x + threadIdx.x;  // over n*32 float4
    if (i < n * 32) {
        int c = i & 31;
        ((float4*)g_agg1)[i] = ((const float4*)b1)[c];
    }
}

// warp per edge: v = h1'[src] * isd[dst], vector RED into agg1
__global__ void k_edge1(const int* __restrict__ src, const int* __restrict__ dst, int e) {
    int gid = blockIdx.x * blockDim.x + threadIdx.x;
    int w = gid >> 5;
    int lane = threadIdx.x & 31;
    if (w >= e) return;
    int s = __ldg(&src[w]);
    int d = __ldg(&dst[w]);
    float sd = __ldg(&g_isd[d]);  // warp-uniform broadcast
    float4 v = ((const float4*)g_h1)[(size_t)s * 32 + lane];
    v.x *= sd; v.y *= sd; v.z *= sd; v.w *= sd;
    float* p = (float*)(((float4*)g_agg1) + ((size_t)d * 32 + lane));
    asm volatile("red.global.add.v4.f32 [%0], {%1,%2,%3,%4};"
                 :: "l"(p), "f"(v.x), "f"(v.y), "f"(v.z), "f"(v.w) : "memory");
}

// ---------------------------------------------------------------- GEMM2 -----
// h2'[N,40] = (relu(agg1)[N,128] @ W2[128,40]) * isd[row]
__global__ void k_gemm2(const float* __restrict__ W2, int n) {
    __shared__ float sW[HID * OUT_DIM];  // 20 KB
    __shared__ float sA[32][129];
    int tid = threadIdx.x;
    int m0 = blockIdx.x * 32;

    for (int i = tid; i < HID * OUT_DIM; i += 256) sW[i] = W2[i];

    #pragma unroll
    for (int j = 0; j < 4; j++) {
        int i = tid + j * 256;
        int r = i >> 5, c = (i & 31) * 4;
        int row = m0 + r;
        float4 v = (row < n) ? *(const float4*)&g_agg1[(size_t)row * HID + c]
                             : make_float4(0.f, 0.f, 0.f, 0.f);
        sA[r][c + 0] = fmaxf(v.x, 0.f);
        sA[r][c + 1] = fmaxf(v.y, 0.f);
        sA[r][c + 2] = fmaxf(v.z, 0.f);
        sA[r][c + 3] = fmaxf(v.w, 0.f);
    }
    __syncthreads();

    int m = tid & 31, g = tid >> 5;
    float acc[5] = {};
    #pragma unroll 8
    for (int k = 0; k < HID; k++) {
        float a = sA[m][k];
        #pragma unroll
        for (int j = 0; j < 5; j++)
            acc[j] = fmaf(a, sW[k * OUT_DIM + g * 5 + j], acc[j]);
    }
    int row = m0 + m;
    if (row < n) {
        float s = g_isd[row];
        #pragma unroll
        for (int j = 0; j < 5; j++)
            g_h2[(size_t)row * OUT_DIM + g * 5 + j] = acc[j] * s;
    }
}

// ------------------------------------------------------- layer2 edge agg ----
__global__ void k_prefill2(const float* __restrict__ b2, float* __restrict__ out, int n) {
    int i = blockIdx.x * blockDim.x + threadIdx.x;  // over n*10 float4
    if (i < n * 10) {
        int c = i - (i / 10) * 10;
        ((float4*)out)[i] = ((const float4*)b2)[c];
    }
}

// thread per (edge, float4-chunk): v = h2'[src]*isd[dst], RED into out
__global__ void k_edge2(const int* __restrict__ src, const int* __restrict__ dst,
                        float* __restrict__ out, int e) {
    int i = blockIdx.x * blockDim.x + threadIdx.x;
    if (i >= e * 10) return;
    int w = i / 10;
    int c = i - w * 10;
    int s = __ldg(&src[w]);
    int d = __ldg(&dst[w]);
    float sd = __ldg(&g_isd[d]);
    float4 v = ((const float4*)g_h2)[(size_t)s * 10 + c];
    v.x *= sd; v.y *= sd; v.z *= sd; v.w *= sd;
    float* p = (float*)(((float4*)out) + ((size_t)d * 10 + c));
    asm volatile("red.global.add.v4.f32 [%0], {%1,%2,%3,%4};"
                 :: "l"(p), "f"(v.x), "f"(v.y), "f"(v.z), "f"(v.w) : "memory");
}

// ---------------------------------------------------------------- launch ----
extern "C" void kernel_launch(void* const* d_in, const int* in_sizes, int n_in,
                              void* d_out, int out_size) {
    const float* x   = (const float*)d_in[0];
    const int*   src = (const int*)d_in[1];
    const int*   dst = (const int*)d_in[2];
    const float* W1  = (const float*)d_in[3];
    const float* b1  = (const float*)d_in[4];
    const float* W2  = (const float*)d_in[5];
    const float* b2  = (const float*)d_in[6];
    float* out = (float*)d_out;

    int n = in_sizes[0] / IN_DIM;
    int e = in_sizes[1];

    k_zero_deg<<<(n + 255) / 256, 256>>>(n);
    k_count<<<(e + 255) / 256, 256>>>(dst, e);
    k_isd<<<(n + 255) / 256, 256>>>(n);

    dim3 g1((n + 127) / 128, 2);
    k_gemm1<<<g1, 256>>>(x, W1, n);
    k_prefill1<<<(n * 32 + 255) / 256, 256>>>(b1, n);
    k_edge1<<<((e * 32) + 255) / 256, 256>>>(src, dst, e);

    k_gemm2<<<(n + 31) / 32, 256>>>(W2, n);
    k_prefill2<<<(n * 10 + 255) / 256, 256>>>(b2, out, n);
    k_edge2<<<((e * 10) + 255) / 256, 256>>>(src, dst, out, e);
}

// round 5
// speedup vs baseline: 1.2687x; 1.2687x over previous
#include <cuda_runtime.h>
#include <cuda_bf16.h>

#define N_NODES 100000
#define N_EDGES 1600000
#define IN_DIM  256
#define HID     128
#define OUT_DIM 40

typedef unsigned long long u64;
typedef unsigned int u32;

// ---- scratch ----
__device__ float g_deg[N_NODES];
__device__ float g_isd[N_NODES];
__device__ float g_h1[(size_t)N_NODES * HID];
__device__ float g_agg1[(size_t)N_NODES * HID];
__device__ float g_h2[(size_t)N_NODES * OUT_DIM];
// W1 split to bf16 hi/lo, transposed to [n][k] (k-contiguous)
__device__ __align__(16) __nv_bfloat16 g_W1hi[HID * IN_DIM];
__device__ __align__(16) __nv_bfloat16 g_W1lo[HID * IN_DIM];

// ---------------------------------------------------------------- degree ----
__global__ void k_zero_deg(int n) {
    int i = blockIdx.x * blockDim.x + threadIdx.x;
    if (i < n) g_deg[i] = 0.f;
}
__global__ void k_count(const int* __restrict__ dst, int e) {
    int i = blockIdx.x * blockDim.x + threadIdx.x;
    if (i < e) atomicAdd(&g_deg[dst[i]], 1.0f);
}
__global__ void k_isd(int n) {
    int i = blockIdx.x * blockDim.x + threadIdx.x;
    if (i < n) {
        float d = g_deg[i];
        g_isd[i] = (d > 0.f) ? rsqrtf(d) : 0.f;
    }
}

// ------------------------------------------------- W1 -> bf16 hi/lo [n][k] --
__global__ void k_splitW1(const float* __restrict__ W1) {
    int i = blockIdx.x * blockDim.x + threadIdx.x;  // 32768
    if (i >= HID * IN_DIM) return;
    int n = i & (HID - 1), k = i >> 7;
    float v = W1[(size_t)k * HID + n];
    __nv_bfloat16 hi = __float2bfloat16(v);
    __nv_bfloat16 lo = __float2bfloat16(v - __bfloat162float(hi));
    g_W1hi[n * IN_DIM + k] = hi;
    g_W1lo[n * IN_DIM + k] = lo;
}

// -------------------------------------------------------------- HMMA GEMM1 --
// h1'[N,128] = (x @ W1) * isd[row], 3xBF16 split via mma.sync.m16n8k16.
// CTA: M=128, N=128(full), K=256 in 4 chunks of 64.
// smem tiles: [row][64 bf16] = 128B rows, SW128 swizzle, 16KB per tile.
// B (W1 hi+lo, all 4 k-chunks) resident: 128KB. A hi/lo chunk: 32KB.
#define A_HI   0
#define A_LO   16384
#define B_OFF  32768
#define SMEM_G1 (B_OFF + 4 * 32768)   // 160 KB

__device__ __forceinline__ u32 toff(int r, int cb) {
    return (u32)((r >> 3) * 1024 + (r & 7) * 128 + (cb ^ ((r & 7) << 4)));
}
__device__ __forceinline__ void ldsm4(u32* r, u32 addr) {
    asm volatile("ldmatrix.sync.aligned.m8n8.x4.shared.b16 {%0,%1,%2,%3}, [%4];"
                 : "=r"(r[0]), "=r"(r[1]), "=r"(r[2]), "=r"(r[3]) : "r"(addr));
}
__device__ __forceinline__ void mma16816(float* c, const u32* a, const u32* b) {
    asm volatile(
        "mma.sync.aligned.m16n8k16.row.col.f32.bf16.bf16.f32 "
        "{%0,%1,%2,%3}, {%4,%5,%6,%7}, {%8,%9}, {%0,%1,%2,%3};"
        : "+f"(c[0]), "+f"(c[1]), "+f"(c[2]), "+f"(c[3])
        : "r"(a[0]), "r"(a[1]), "r"(a[2]), "r"(a[3]), "r"(b[0]), "r"(b[1]));
}

__global__ void __launch_bounds__(256, 1)
k_gemm1(const float* __restrict__ x, int n) {
    extern __shared__ char smem[];
    u32 sb;
    asm("{ .reg .u64 t; cvta.to.shared.u64 t, %1; cvt.u32.u64 %0, t; }"
        : "=r"(sb) : "l"(smem));
    const int tid = threadIdx.x;
    const int l = tid & 31;
    const int wid = tid >> 5;
    const int wm = wid & 3;        // 4 warps over M (32 rows each)
    const int wn = wid >> 2;       // 2 warps over N (64 cols each)
    const int m0 = blockIdx.x * 128;

    // ---- stage B (whole W1 hi/lo, swizzled, chunked by k64) ----
    #pragma unroll 1
    for (int ch = 0; ch < 4; ch++) {
        char* bh = smem + B_OFF + ch * 32768;
        char* bl = bh + 16384;
        #pragma unroll
        for (int j = 0; j < 8; j++) {
            int u = tid + j * 256;
            int r = u >> 4, kq = (u & 15) * 4;
            u32 off = toff(r, kq * 2);
            *(uint2*)(bh + off) = *(const uint2*)&g_W1hi[r * IN_DIM + ch * 64 + kq];
            *(uint2*)(bl + off) = *(const uint2*)&g_W1lo[r * IN_DIM + ch * 64 + kq];
        }
    }

    // ---- prefetch A chunk 0 into regs ----
    float4 ra[8];
    {
        #pragma unroll
        for (int j = 0; j < 8; j++) {
            int u = tid + j * 256;
            int r = u >> 4, kq = (u & 15) * 4;
            int row = m0 + r;
            ra[j] = (row < n) ? *(const float4*)&x[(size_t)row * IN_DIM + kq]
                              : make_float4(0.f, 0.f, 0.f, 0.f);
        }
    }

    float acc[2][8][4] = {};

    // per-lane ldmatrix address components
    u32 PA[2], XA[2];
    #pragma unroll
    for (int mb = 0; mb < 2; mb++) {
        int r = wm * 32 + mb * 16 + (l & 7) + 8 * ((l >> 3) & 1);
        PA[mb] = (u32)((r >> 3) * 1024 + (r & 7) * 128);
        XA[mb] = (u32)((r & 7) << 4);
    }
    u32 cblA = 16 * (l >> 4);
    u32 PB[4], XB[4];
    #pragma unroll
    for (int nb = 0; nb < 4; nb++) {
        int r = wn * 64 + nb * 16 + (l & 7) + 8 * ((l >> 4) & 1);
        PB[nb] = (u32)((r >> 3) * 1024 + (r & 7) * 128);
        XB[nb] = (u32)((r & 7) << 4);
    }
    u32 cblB = 16 * ((l >> 3) & 1);

    #pragma unroll 1
    for (int ch = 0; ch < 4; ch++) {
        // convert prefetched A -> smem hi/lo (swizzled)
        #pragma unroll
        for (int j = 0; j < 8; j++) {
            int u = tid + j * 256;
            int r = u >> 4, kq = (u & 15) * 4;
            float4 v = ra[j];
            __nv_bfloat16 h0 = __float2bfloat16(v.x), h1b = __float2bfloat16(v.y);
            __nv_bfloat16 h2 = __float2bfloat16(v.z), h3 = __float2bfloat16(v.w);
            __nv_bfloat16 l0 = __float2bfloat16(v.x - __bfloat162float(h0));
            __nv_bfloat16 l1 = __float2bfloat16(v.y - __bfloat162float(h1b));
            __nv_bfloat16 l2 = __float2bfloat16(v.z - __bfloat162float(h2));
            __nv_bfloat16 l3 = __float2bfloat16(v.w - __bfloat162float(h3));
            u32 off = toff(r, kq * 2);
            __nv_bfloat162 ph0 = __halves2bfloat162(h0, h1b);
            __nv_bfloat162 ph1 = __halves2bfloat162(h2, h3);
            __nv_bfloat162 pl0 = __halves2bfloat162(l0, l1);
            __nv_bfloat162 pl1 = __halves2bfloat162(l2, l3);
            *(uint2*)(smem + A_HI + off) = make_uint2(*(u32*)&ph0, *(u32*)&ph1);
            *(uint2*)(smem + A_LO + off) = make_uint2(*(u32*)&pl0, *(u32*)&pl1);
        }
        __syncthreads();

        // prefetch next A chunk
        if (ch < 3) {
            int k0 = (ch + 1) * 64;
            #pragma unroll
            for (int j = 0; j < 8; j++) {
                int u = tid + j * 256;
                int r = u >> 4, kq = (u & 15) * 4;
                int row = m0 + r;
                ra[j] = (row < n) ? *(const float4*)&x[(size_t)row * IN_DIM + k0 + kq]
                                  : make_float4(0.f, 0.f, 0.f, 0.f);
            }
        }

        u32 baseBh = sb + B_OFF + ch * 32768;
        u32 baseBl = baseBh + 16384;
        #pragma unroll
        for (int ks = 0; ks < 4; ks++) {
            u32 kb = ks * 32;
            u32 Ah[2][4], Al[2][4], Bh[4][4], Bl[4][4];
            #pragma unroll
            for (int mb = 0; mb < 2; mb++) {
                u32 aoff = PA[mb] + ((kb + cblA) ^ XA[mb]);
                ldsm4(Ah[mb], sb + A_HI + aoff);
                ldsm4(Al[mb], sb + A_LO + aoff);
            }
            #pragma unroll
            for (int nb = 0; nb < 4; nb++) {
                u32 boff = PB[nb] + ((kb + cblB) ^ XB[nb]);
                ldsm4(Bh[nb], baseBh + boff);
                ldsm4(Bl[nb], baseBl + boff);
            }
            #pragma unroll
            for (int mb = 0; mb < 2; mb++)
                #pragma unroll
                for (int nb = 0; nb < 4; nb++)
                    #pragma unroll
                    for (int j = 0; j < 2; j++) {
                        float* c = acc[mb][nb * 2 + j];
                        mma16816(c, Ah[mb], &Bh[nb][2 * j]);
                        mma16816(c, Ah[mb], &Bl[nb][2 * j]);
                        mma16816(c, Al[mb], &Bh[nb][2 * j]);
                    }
        }
        __syncthreads();
    }

    // ---- epilogue: scale by isd[row], store ----
    #pragma unroll
    for (int mb = 0; mb < 2; mb++) {
        int r0 = m0 + wm * 32 + mb * 16 + (l >> 2);
        int r1 = r0 + 8;
        float s0 = (r0 < n) ? g_isd[r0] : 0.f;
        float s1 = (r1 < n) ? g_isd[r1] : 0.f;
        #pragma unroll
        for (int idx = 0; idx < 8; idx++) {
            int col = wn * 64 + idx * 8 + (l & 3) * 2;
            float* c = acc[mb][idx];
            if (r0 < n)
                *(float2*)&g_h1[(size_t)r0 * HID + col] = make_float2(c[0] * s0, c[1] * s0);
            if (r1 < n)
                *(float2*)&g_h1[(size_t)r1 * HID + col] = make_float2(c[2] * s1, c[3] * s1);
        }
    }
}

// ------------------------------------------------------- layer1 edge agg ----
__global__ void k_prefill1(const float* __restrict__ b1, int n) {
    int i = blockIdx.x * blockDim.x + threadIdx.x;
    if (i < n * 32) {
        int c = i & 31;
        ((float4*)g_agg1)[i] = ((const float4*)b1)[c];
    }
}

__global__ void k_edge1(const int* __restrict__ src, const int* __restrict__ dst, int e) {
    int gid = blockIdx.x * blockDim.x + threadIdx.x;
    int w = gid >> 5;
    int lane = threadIdx.x & 31;
    if (w >= e) return;
    int s = __ldg(&src[w]);
    int d = __ldg(&dst[w]);
    float sd = __ldg(&g_isd[d]);
    float4 v = ((const float4*)g_h1)[(size_t)s * 32 + lane];
    v.x *= sd; v.y *= sd; v.z *= sd; v.w *= sd;
    float* p = (float*)(((float4*)g_agg1) + ((size_t)d * 32 + lane));
    asm volatile("red.global.add.v4.f32 [%0], {%1,%2,%3,%4};"
                 :: "l"(p), "f"(v.x), "f"(v.y), "f"(v.z), "f"(v.w) : "memory");
}

// ---------------------------------------------------------------- GEMM2 -----
__global__ void k_gemm2(const float* __restrict__ W2, int n) {
    __shared__ float sW[HID * OUT_DIM];
    __shared__ float sA[32][129];
    int tid = threadIdx.x;
    int m0 = blockIdx.x * 32;

    for (int i = tid; i < HID * OUT_DIM; i += 256) sW[i] = W2[i];

    #pragma unroll
    for (int j = 0; j < 4; j++) {
        int i = tid + j * 256;
        int r = i >> 5, c = (i & 31) * 4;
        int row = m0 + r;
        float4 v = (row < n) ? *(const float4*)&g_agg1[(size_t)row * HID + c]
                             : make_float4(0.f, 0.f, 0.f, 0.f);
        sA[r][c + 0] = fmaxf(v.x, 0.f);
        sA[r][c + 1] = fmaxf(v.y, 0.f);
        sA[r][c + 2] = fmaxf(v.z, 0.f);
        sA[r][c + 3] = fmaxf(v.w, 0.f);
    }
    __syncthreads();

    int m = tid & 31, g = tid >> 5;
    float acc[5] = {};
    #pragma unroll 8
    for (int k = 0; k < HID; k++) {
        float a = sA[m][k];
        #pragma unroll
        for (int j = 0; j < 5; j++)
            acc[j] = fmaf(a, sW[k * OUT_DIM + g * 5 + j], acc[j]);
    }
    int row = m0 + m;
    if (row < n) {
        float s = g_isd[row];
        #pragma unroll
        for (int j = 0; j < 5; j++)
            g_h2[(size_t)row * OUT_DIM + g * 5 + j] = acc[j] * s;
    }
}

// ------------------------------------------------------- layer2 edge agg ----
__global__ void k_prefill2(const float* __restrict__ b2, float* __restrict__ out, int n) {
    int i = blockIdx.x * blockDim.x + threadIdx.x;
    if (i < n * 10) {
        int c = i - (i / 10) * 10;
        ((float4*)out)[i] = ((const float4*)b2)[c];
    }
}

__global__ void k_edge2(const int* __restrict__ src, const int* __restrict__ dst,
                        float* __restrict__ out, int e) {
    int i = blockIdx.x * blockDim.x + threadIdx.x;
    if (i >= e * 10) return;
    int w = i / 10;
    int c = i - w * 10;
    int s = __ldg(&src[w]);
    int d = __ldg(&dst[w]);
    float sd = __ldg(&g_isd[d]);
    float4 v = ((const float4*)g_h2)[(size_t)s * 10 + c];
    v.x *= sd; v.y *= sd; v.z *= sd; v.w *= sd;
    float* p = (float*)(((float4*)out) + ((size_t)d * 10 + c));
    asm volatile("red.global.add.v4.f32 [%0], {%1,%2,%3,%4};"
                 :: "l"(p), "f"(v.x), "f"(v.y), "f"(v.z), "f"(v.w) : "memory");
}

// ---------------------------------------------------------------- launch ----
extern "C" void kernel_launch(void* const* d_in, const int* in_sizes, int n_in,
                              void* d_out, int out_size) {
    const float* x   = (const float*)d_in[0];
    const int*   src = (const int*)d_in[1];
    const int*   dst = (const int*)d_in[2];
    const float* W1  = (const float*)d_in[3];
    const float* b1  = (const float*)d_in[4];
    const float* W2  = (const float*)d_in[5];
    const float* b2  = (const float*)d_in[6];
    float* out = (float*)d_out;

    int n = in_sizes[0] / IN_DIM;
    int e = in_sizes[1];

    static int smem_set = 0;
    if (!smem_set) {
        cudaFuncSetAttribute(k_gemm1, cudaFuncAttributeMaxDynamicSharedMemorySize,
                             SMEM_G1);
        smem_set = 1;
    }

    k_zero_deg<<<(n + 255) / 256, 256>>>(n);
    k_count<<<(e + 255) / 256, 256>>>(dst, e);
    k_isd<<<(n + 255) / 256, 256>>>(n);
    k_splitW1<<<(HID * IN_DIM + 255) / 256, 256>>>(W1);

    k_gemm1<<<(n + 127) / 128, 256, SMEM_G1>>>(x, n);
    k_prefill1<<<(n * 32 + 255) / 256, 256>>>(b1, n);
    k_edge1<<<((e * 32) + 255) / 256, 256>>>(src, dst, e);

    k_gemm2<<<(n + 31) / 32, 256>>>(W2, n);
    k_prefill2<<<(n * 10 + 255) / 256, 256>>>(b2, out, n);
    k_edge2<<<((e * 10) + 255) / 256, 256>>>(src, dst, out, e);
}

// round 6
// speedup vs baseline: 1.9719x; 1.5542x over previous
#include <cuda_runtime.h>
#include <cuda_bf16.h>

#define N_NODES 100000
#define N_EDGES 1600000
#define IN_DIM  256
#define HID     128
#define OUT_DIM 40
#define SCAN_BS 1024
#define NB_SCAN ((N_NODES + SCAN_BS - 1) / SCAN_BS)

typedef unsigned long long u64;
typedef unsigned int u32;

// ---- scratch ----
__device__ float g_deg[N_NODES];
__device__ float g_isd[N_NODES];
__device__ float g_h1[(size_t)N_NODES * HID];
__device__ float g_agg1[(size_t)N_NODES * HID];
__device__ float g_h2[(size_t)N_NODES * OUT_DIM];
__device__ __align__(16) __nv_bfloat16 g_W1hi[HID * IN_DIM];
__device__ __align__(16) __nv_bfloat16 g_W1lo[HID * IN_DIM];
// CSR by dst
__device__ int g_rowstart[N_NODES + 1];
__device__ int g_cursor[N_NODES];
__device__ int g_bsum[NB_SCAN];
__device__ int g_elist[N_EDGES];

// ---------------------------------------------------------------- degree ----
__global__ void k_zero_deg(int n) {
    int i = blockIdx.x * blockDim.x + threadIdx.x;
    if (i < n) g_deg[i] = 0.f;
}
__global__ void k_count(const int* __restrict__ dst, int e) {
    int i = blockIdx.x * blockDim.x + threadIdx.x;
    if (i < e) atomicAdd(&g_deg[dst[i]], 1.0f);
}
__global__ void k_isd(int n) {
    int i = blockIdx.x * blockDim.x + threadIdx.x;
    if (i < n) {
        float d = g_deg[i];
        g_isd[i] = (d > 0.f) ? rsqrtf(d) : 0.f;
    }
}

// ----------------------------------------------------------- CSR build ------
__global__ void k_scan1(int n) {
    __shared__ int sm[SCAN_BS];
    int t = threadIdx.x;
    int idx = blockIdx.x * SCAN_BS + t;
    int v = (idx < n) ? (int)g_deg[idx] : 0;
    sm[t] = v;
    __syncthreads();
    #pragma unroll
    for (int off = 1; off < SCAN_BS; off <<= 1) {
        int y = (t >= off) ? sm[t - off] : 0;
        __syncthreads();
        sm[t] += y;
        __syncthreads();
    }
    if (idx < n) g_rowstart[idx] = sm[t] - v;   // exclusive (block-local)
    if (t == SCAN_BS - 1) g_bsum[blockIdx.x] = sm[t];
}
__global__ void k_scan2(int n, int e) {
    if (threadIdx.x == 0) {
        int run = 0;
        for (int i = 0; i < NB_SCAN; i++) {
            int t = g_bsum[i];
            g_bsum[i] = run;
            run += t;
        }
        g_rowstart[n] = run;  // == e
    }
}
__global__ void k_scan3(int n) {
    int i = blockIdx.x * blockDim.x + threadIdx.x;
    if (i < n) {
        int rs = g_rowstart[i] + g_bsum[i >> 10];
        g_rowstart[i] = rs;
        g_cursor[i] = rs;
    }
}
__global__ void k_scatter(const int* __restrict__ src, const int* __restrict__ dst, int e) {
    int i = blockIdx.x * blockDim.x + threadIdx.x;
    if (i < e) {
        int pos = atomicAdd(&g_cursor[dst[i]], 1);
        g_elist[pos] = src[i];
    }
}

// ------------------------------------------------- W1 -> bf16 hi/lo [n][k] --
__global__ void k_splitW1(const float* __restrict__ W1) {
    int i = blockIdx.x * blockDim.x + threadIdx.x;
    if (i >= HID * IN_DIM) return;
    int n = i & (HID - 1), k = i >> 7;
    float v = W1[(size_t)k * HID + n];
    __nv_bfloat16 hi = __float2bfloat16(v);
    __nv_bfloat16 lo = __float2bfloat16(v - __bfloat162float(hi));
    g_W1hi[n * IN_DIM + k] = hi;
    g_W1lo[n * IN_DIM + k] = lo;
}

// -------------------------------------------------------------- HMMA GEMM1 --
#define A_HI   0
#define A_LO   16384
#define B_OFF  32768
#define SMEM_G1 (B_OFF + 4 * 32768)   // 160 KB

__device__ __forceinline__ u32 toff(int r, int cb) {
    return (u32)((r >> 3) * 1024 + (r & 7) * 128 + (cb ^ ((r & 7) << 4)));
}
__device__ __forceinline__ void ldsm4(u32* r, u32 addr) {
    asm volatile("ldmatrix.sync.aligned.m8n8.x4.shared.b16 {%0,%1,%2,%3}, [%4];"
                 : "=r"(r[0]), "=r"(r[1]), "=r"(r[2]), "=r"(r[3]) : "r"(addr));
}
__device__ __forceinline__ void mma16816(float* c, const u32* a, const u32* b) {
    asm volatile(
        "mma.sync.aligned.m16n8k16.row.col.f32.bf16.bf16.f32 "
        "{%0,%1,%2,%3}, {%4,%5,%6,%7}, {%8,%9}, {%0,%1,%2,%3};"
        : "+f"(c[0]), "+f"(c[1]), "+f"(c[2]), "+f"(c[3])
        : "r"(a[0]), "r"(a[1]), "r"(a[2]), "r"(a[3]), "r"(b[0]), "r"(b[1]));
}

__global__ void __launch_bounds__(256, 1)
k_gemm1(const float* __restrict__ x, int n) {
    extern __shared__ char smem[];
    u32 sb;
    asm("{ .reg .u64 t; cvta.to.shared.u64 t, %1; cvt.u32.u64 %0, t; }"
        : "=r"(sb) : "l"(smem));
    const int tid = threadIdx.x;
    const int l = tid & 31;
    const int wid = tid >> 5;
    const int wm = wid & 3;
    const int wn = wid >> 2;
    const int m0 = blockIdx.x * 128;

    #pragma unroll 1
    for (int ch = 0; ch < 4; ch++) {
        char* bh = smem + B_OFF + ch * 32768;
        char* bl = bh + 16384;
        #pragma unroll
        for (int j = 0; j < 8; j++) {
            int u = tid + j * 256;
            int r = u >> 4, kq = (u & 15) * 4;
            u32 off = toff(r, kq * 2);
            *(uint2*)(bh + off) = *(const uint2*)&g_W1hi[r * IN_DIM + ch * 64 + kq];
            *(uint2*)(bl + off) = *(const uint2*)&g_W1lo[r * IN_DIM + ch * 64 + kq];
        }
    }

    float4 ra[8];
    #pragma unroll
    for (int j = 0; j < 8; j++) {
        int u = tid + j * 256;
        int r = u >> 4, kq = (u & 15) * 4;
        int row = m0 + r;
        ra[j] = (row < n) ? *(const float4*)&x[(size_t)row * IN_DIM + kq]
                          : make_float4(0.f, 0.f, 0.f, 0.f);
    }

    float acc[2][8][4] = {};

    u32 PA[2], XA[2];
    #pragma unroll
    for (int mb = 0; mb < 2; mb++) {
        int r = wm * 32 + mb * 16 + (l & 7) + 8 * ((l >> 3) & 1);
        PA[mb] = (u32)((r >> 3) * 1024 + (r & 7) * 128);
        XA[mb] = (u32)((r & 7) << 4);
    }
    u32 cblA = 16 * (l >> 4);
    u32 PB[4], XB[4];
    #pragma unroll
    for (int nb = 0; nb < 4; nb++) {
        int r = wn * 64 + nb * 16 + (l & 7) + 8 * ((l >> 4) & 1);
        PB[nb] = (u32)((r >> 3) * 1024 + (r & 7) * 128);
        XB[nb] = (u32)((r & 7) << 4);
    }
    u32 cblB = 16 * ((l >> 3) & 1);

    #pragma unroll 1
    for (int ch = 0; ch < 4; ch++) {
        #pragma unroll
        for (int j = 0; j < 8; j++) {
            int u = tid + j * 256;
            int r = u >> 4, kq = (u & 15) * 4;
            float4 v = ra[j];
            __nv_bfloat16 h0 = __float2bfloat16(v.x), h1b = __float2bfloat16(v.y);
            __nv_bfloat16 h2 = __float2bfloat16(v.z), h3 = __float2bfloat16(v.w);
            __nv_bfloat16 l0 = __float2bfloat16(v.x - __bfloat162float(h0));
            __nv_bfloat16 l1 = __float2bfloat16(v.y - __bfloat162float(h1b));
            __nv_bfloat16 l2 = __float2bfloat16(v.z - __bfloat162float(h2));
            __nv_bfloat16 l3 = __float2bfloat16(v.w - __bfloat162float(h3));
            u32 off = toff(r, kq * 2);
            __nv_bfloat162 ph0 = __halves2bfloat162(h0, h1b);
            __nv_bfloat162 ph1 = __halves2bfloat162(h2, h3);
            __nv_bfloat162 pl0 = __halves2bfloat162(l0, l1);
            __nv_bfloat162 pl1 = __halves2bfloat162(l2, l3);
            *(uint2*)(smem + A_HI + off) = make_uint2(*(u32*)&ph0, *(u32*)&ph1);
            *(uint2*)(smem + A_LO + off) = make_uint2(*(u32*)&pl0, *(u32*)&pl1);
        }
        __syncthreads();

        if (ch < 3) {
            int k0 = (ch + 1) * 64;
            #pragma unroll
            for (int j = 0; j < 8; j++) {
                int u = tid + j * 256;
                int r = u >> 4, kq = (u & 15) * 4;
                int row = m0 + r;
                ra[j] = (row < n) ? *(const float4*)&x[(size_t)row * IN_DIM + k0 + kq]
                                  : make_float4(0.f, 0.f, 0.f, 0.f);
            }
        }

        u32 baseBh = sb + B_OFF + ch * 32768;
        u32 baseBl = baseBh + 16384;
        #pragma unroll
        for (int ks = 0; ks < 4; ks++) {
            u32 kb = ks * 32;
            u32 Ah[2][4], Al[2][4], Bh[4][4], Bl[4][4];
            #pragma unroll
            for (int mb = 0; mb < 2; mb++) {
                u32 aoff = PA[mb] + ((kb + cblA) ^ XA[mb]);
                ldsm4(Ah[mb], sb + A_HI + aoff);
                ldsm4(Al[mb], sb + A_LO + aoff);
            }
            #pragma unroll
            for (int nb = 0; nb < 4; nb++) {
                u32 boff = PB[nb] + ((kb + cblB) ^ XB[nb]);
                ldsm4(Bh[nb], baseBh + boff);
                ldsm4(Bl[nb], baseBl + boff);
            }
            #pragma unroll
            for (int mb = 0; mb < 2; mb++)
                #pragma unroll
                for (int nb = 0; nb < 4; nb++)
                    #pragma unroll
                    for (int j = 0; j < 2; j++) {
                        float* c = acc[mb][nb * 2 + j];
                        mma16816(c, Ah[mb], &Bh[nb][2 * j]);
                        mma16816(c, Ah[mb], &Bl[nb][2 * j]);
                        mma16816(c, Al[mb], &Bh[nb][2 * j]);
                    }
        }
        __syncthreads();
    }

    #pragma unroll
    for (int mb = 0; mb < 2; mb++) {
        int r0 = m0 + wm * 32 + mb * 16 + (l >> 2);
        int r1 = r0 + 8;
        float s0 = (r0 < n) ? g_isd[r0] : 0.f;
        float s1 = (r1 < n) ? g_isd[r1] : 0.f;
        #pragma unroll
        for (int idx = 0; idx < 8; idx++) {
            int col = wn * 64 + idx * 8 + (l & 3) * 2;
            float* c = acc[mb][idx];
            if (r0 < n)
                *(float2*)&g_h1[(size_t)r0 * HID + col] = make_float2(c[0] * s0, c[1] * s0);
            if (r1 < n)
                *(float2*)&g_h1[(size_t)r1 * HID + col] = make_float2(c[2] * s1, c[3] * s1);
        }
    }
}

// -------------------------------------------------- layer1 CSR aggregation --
// warp per node: agg1[d] = isd[d] * sum_{j in in(d)} h1'[elist[j]] + b1
__global__ void k_agg1(const float* __restrict__ b1, int n) {
    int gid = blockIdx.x * blockDim.x + threadIdx.x;
    int node = gid >> 5;
    int lane = threadIdx.x & 31;
    if (node >= n) return;
    int beg = g_rowstart[node];
    int end = g_rowstart[node + 1];
    float4 acc = make_float4(0.f, 0.f, 0.f, 0.f);
    const float4* h1 = (const float4*)g_h1;
    int j = beg;
    for (; j + 4 <= end; j += 4) {
        int s0 = g_elist[j], s1 = g_elist[j + 1];
        int s2 = g_elist[j + 2], s3 = g_elist[j + 3];
        float4 v0 = h1[(size_t)s0 * 32 + lane];
        float4 v1 = h1[(size_t)s1 * 32 + lane];
        float4 v2 = h1[(size_t)s2 * 32 + lane];
        float4 v3 = h1[(size_t)s3 * 32 + lane];
        acc.x += v0.x + v1.x + v2.x + v3.x;
        acc.y += v0.y + v1.y + v2.y + v3.y;
        acc.z += v0.z + v1.z + v2.z + v3.z;
        acc.w += v0.w + v1.w + v2.w + v3.w;
    }
    for (; j < end; j++) {
        int s = g_elist[j];
        float4 v = h1[(size_t)s * 32 + lane];
        acc.x += v.x; acc.y += v.y; acc.z += v.z; acc.w += v.w;
    }
    float sd = g_isd[node];
    float4 bb = ((const float4*)b1)[lane];
    float4 o = make_float4(fmaf(sd, acc.x, bb.x), fmaf(sd, acc.y, bb.y),
                           fmaf(sd, acc.z, bb.z), fmaf(sd, acc.w, bb.w));
    ((float4*)g_agg1)[(size_t)node * 32 + lane] = o;
}

// ---------------------------------------------------------------- GEMM2 -----
__global__ void k_gemm2(const float* __restrict__ W2, int n) {
    __shared__ float sW[HID * OUT_DIM];
    __shared__ float sA[32][129];
    int tid = threadIdx.x;
    int m0 = blockIdx.x * 32;

    for (int i = tid; i < HID * OUT_DIM; i += 256) sW[i] = W2[i];

    #pragma unroll
    for (int j = 0; j < 4; j++) {
        int i = tid + j * 256;
        int r = i >> 5, c = (i & 31) * 4;
        int row = m0 + r;
        float4 v = (row < n) ? *(const float4*)&g_agg1[(size_t)row * HID + c]
                             : make_float4(0.f, 0.f, 0.f, 0.f);
        sA[r][c + 0] = fmaxf(v.x, 0.f);
        sA[r][c + 1] = fmaxf(v.y, 0.f);
        sA[r][c + 2] = fmaxf(v.z, 0.f);
        sA[r][c + 3] = fmaxf(v.w, 0.f);
    }
    __syncthreads();

    int m = tid & 31, g = tid >> 5;
    float acc[5] = {};
    #pragma unroll 8
    for (int k = 0; k < HID; k++) {
        float a = sA[m][k];
        #pragma unroll
        for (int j = 0; j < 5; j++)
            acc[j] = fmaf(a, sW[k * OUT_DIM + g * 5 + j], acc[j]);
    }
    int row = m0 + m;
    if (row < n) {
        float s = g_isd[row];
        #pragma unroll
        for (int j = 0; j < 5; j++)
            g_h2[(size_t)row * OUT_DIM + g * 5 + j] = acc[j] * s;
    }
}

// -------------------------------------------------- layer2 CSR aggregation --
// thread per (node, float4-chunk c<10): out = isd[d]*sum h2'[src] + b2
__global__ void k_agg2(const float* __restrict__ b2, float* __restrict__ out, int n) {
    int i = blockIdx.x * blockDim.x + threadIdx.x;
    if (i >= n * 10) return;
    int node = i / 10;
    int c = i - node * 10;
    int beg = g_rowstart[node];
    int end = g_rowstart[node + 1];
    const float4* h2 = (const float4*)g_h2;
    float4 acc = make_float4(0.f, 0.f, 0.f, 0.f);
    int j = beg;
    for (; j + 4 <= end; j += 4) {
        int s0 = g_elist[j], s1 = g_elist[j + 1];
        int s2 = g_elist[j + 2], s3 = g_elist[j + 3];
        float4 v0 = h2[(size_t)s0 * 10 + c];
        float4 v1 = h2[(size_t)s1 * 10 + c];
        float4 v2 = h2[(size_t)s2 * 10 + c];
        float4 v3 = h2[(size_t)s3 * 10 + c];
        acc.x += v0.x + v1.x + v2.x + v3.x;
        acc.y += v0.y + v1.y + v2.y + v3.y;
        acc.z += v0.z + v1.z + v2.z + v3.z;
        acc.w += v0.w + v1.w + v2.w + v3.w;
    }
    for (; j < end; j++) {
        int s = g_elist[j];
        float4 v = h2[(size_t)s * 10 + c];
        acc.x += v.x; acc.y += v.y; acc.z += v.z; acc.w += v.w;
    }
    float sd = g_isd[node];
    float4 bb = ((const float4*)b2)[c];
    ((float4*)out)[i] = make_float4(fmaf(sd, acc.x, bb.x), fmaf(sd, acc.y, bb.y),
                                    fmaf(sd, acc.z, bb.z), fmaf(sd, acc.w, bb.w));
}

// ---------------------------------------------------------------- launch ----
extern "C" void kernel_launch(void* const* d_in, const int* in_sizes, int n_in,
                              void* d_out, int out_size) {
    const float* x   = (const float*)d_in[0];
    const int*   src = (const int*)d_in[1];
    const int*   dst = (const int*)d_in[2];
    const float* W1  = (const float*)d_in[3];
    const float* b1  = (const float*)d_in[4];
    const float* W2  = (const float*)d_in[5];
    const float* b2  = (const float*)d_in[6];
    float* out = (float*)d_out;

    int n = in_sizes[0] / IN_DIM;
    int e = in_sizes[1];

    static int smem_set = 0;
    if (!smem_set) {
        cudaFuncSetAttribute(k_gemm1, cudaFuncAttributeMaxDynamicSharedMemorySize,
                             SMEM_G1);
        smem_set = 1;
    }

    k_zero_deg<<<(n + 255) / 256, 256>>>(n);
    k_count<<<(e + 255) / 256, 256>>>(dst, e);
    k_isd<<<(n + 255) / 256, 256>>>(n);
    k_splitW1<<<(HID * IN_DIM + 255) / 256, 256>>>(W1);

    // CSR build (overlaps conceptually with gemm1's weight prep; same stream)
    k_scan1<<<NB_SCAN, SCAN_BS>>>(n);
    k_scan2<<<1, 32>>>(n, e);
    k_scan3<<<(n + 255) / 256, 256>>>(n);
    k_scatter<<<(e + 255) / 256, 256>>>(src, dst, e);

    k_gemm1<<<(n + 127) / 128, 256, SMEM_G1>>>(x, n);
    k_agg1<<<((n * 32) + 255) / 256, 256>>>(b1, n);

    k_gemm2<<<(n + 31) / 32, 256>>>(W2, n);
    k_agg2<<<(n * 10 + 255) / 256, 256>>>(b2, out, n);
}

// round 7
// speedup vs baseline: 2.0036x; 1.0161x over previous
#include <cuda_runtime.h>
#include <cuda_bf16.h>

#define N_NODES 100000
#define N_EDGES 1600000
#define IN_DIM  256
#define HID     128
#define OUT_DIM 40
#define SCAN_BS 1024
#define NB_SCAN ((N_NODES + SCAN_BS - 1) / SCAN_BS)

typedef unsigned long long u64;
typedef unsigned int u32;

// ---- scratch ----
__device__ float g_deg[N_NODES];
__device__ float g_isd[N_NODES];
__device__ float g_h1[(size_t)N_NODES * HID];     // UNSCALED x@W1
__device__ float g_h2[(size_t)N_NODES * OUT_DIM]; // isd-scaled layer2 transform
__device__ __align__(16) __nv_bfloat16 g_W1hi[HID * IN_DIM];
__device__ __align__(16) __nv_bfloat16 g_W1lo[HID * IN_DIM];
// CSR by dst
__device__ int g_rowstart[N_NODES + 1];
__device__ int g_cursor[N_NODES];
__device__ int g_bsum[NB_SCAN];
__device__ int g_elist[N_EDGES];

// ---------------------------------------------------------------- degree ----
__global__ void k_zero_deg(int n) {
    int i = blockIdx.x * blockDim.x + threadIdx.x;
    if (i < n) g_deg[i] = 0.f;
}
__global__ void k_count(const int* __restrict__ dst, int e) {
    int i = blockIdx.x * blockDim.x + threadIdx.x;
    if (i < e) atomicAdd(&g_deg[dst[i]], 1.0f);
}
__global__ void k_isd(int n) {
    int i = blockIdx.x * blockDim.x + threadIdx.x;
    if (i < n) {
        float d = g_deg[i];
        g_isd[i] = (d > 0.f) ? rsqrtf(d) : 0.f;
    }
}

// ----------------------------------------------------------- CSR build ------
__global__ void k_scan1(int n) {
    __shared__ int sm[SCAN_BS];
    int t = threadIdx.x;
    int idx = blockIdx.x * SCAN_BS + t;
    int v = (idx < n) ? (int)g_deg[idx] : 0;
    sm[t] = v;
    __syncthreads();
    #pragma unroll
    for (int off = 1; off < SCAN_BS; off <<= 1) {
        int y = (t >= off) ? sm[t - off] : 0;
        __syncthreads();
        sm[t] += y;
        __syncthreads();
    }
    if (idx < n) g_rowstart[idx] = sm[t] - v;
    if (t == SCAN_BS - 1) g_bsum[blockIdx.x] = sm[t];
}
__global__ void k_scan2(int n, int e) {
    if (threadIdx.x == 0) {
        int run = 0;
        for (int i = 0; i < NB_SCAN; i++) {
            int t = g_bsum[i];
            g_bsum[i] = run;
            run += t;
        }
        g_rowstart[n] = run;
    }
}
__global__ void k_scan3(int n) {
    int i = blockIdx.x * blockDim.x + threadIdx.x;
    if (i < n) {
        int rs = g_rowstart[i] + g_bsum[i >> 10];
        g_rowstart[i] = rs;
        g_cursor[i] = rs;
    }
}
__global__ void k_scatter(const int* __restrict__ src, const int* __restrict__ dst, int e) {
    int i = blockIdx.x * blockDim.x + threadIdx.x;
    if (i < e) {
        int pos = atomicAdd(&g_cursor[dst[i]], 1);
        g_elist[pos] = src[i];
    }
}

// ------------------------------------------------- W1 -> bf16 hi/lo [n][k] --
__global__ void k_splitW1(const float* __restrict__ W1) {
    int i = blockIdx.x * blockDim.x + threadIdx.x;
    if (i >= HID * IN_DIM) return;
    int n = i & (HID - 1), k = i >> 7;
    float v = W1[(size_t)k * HID + n];
    __nv_bfloat16 hi = __float2bfloat16(v);
    __nv_bfloat16 lo = __float2bfloat16(v - __bfloat162float(hi));
    g_W1hi[n * IN_DIM + k] = hi;
    g_W1lo[n * IN_DIM + k] = lo;
}

// -------------------------------------------------------------- HMMA GEMM1 --
#define A_HI   0
#define A_LO   16384
#define B_OFF  32768
#define SMEM_G1 (B_OFF + 4 * 32768)   // 160 KB

__device__ __forceinline__ u32 toff(int r, int cb) {
    return (u32)((r >> 3) * 1024 + (r & 7) * 128 + (cb ^ ((r & 7) << 4)));
}
__device__ __forceinline__ void ldsm4(u32* r, u32 addr) {
    asm volatile("ldmatrix.sync.aligned.m8n8.x4.shared.b16 {%0,%1,%2,%3}, [%4];"
                 : "=r"(r[0]), "=r"(r[1]), "=r"(r[2]), "=r"(r[3]) : "r"(addr));
}
__device__ __forceinline__ void mma16816(float* c, const u32* a, const u32* b) {
    asm volatile(
        "mma.sync.aligned.m16n8k16.row.col.f32.bf16.bf16.f32 "
        "{%0,%1,%2,%3}, {%4,%5,%6,%7}, {%8,%9}, {%0,%1,%2,%3};"
        : "+f"(c[0]), "+f"(c[1]), "+f"(c[2]), "+f"(c[3])
        : "r"(a[0]), "r"(a[1]), "r"(a[2]), "r"(a[3]), "r"(b[0]), "r"(b[1]));
}

__global__ void __launch_bounds__(256, 1)
k_gemm1(const float* __restrict__ x, int n) {
    extern __shared__ char smem[];
    u32 sb;
    asm("{ .reg .u64 t; cvta.to.shared.u64 t, %1; cvt.u32.u64 %0, t; }"
        : "=r"(sb) : "l"(smem));
    const int tid = threadIdx.x;
    const int l = tid & 31;
    const int wid = tid >> 5;
    const int wm = wid & 3;
    const int wn = wid >> 2;
    const int m0 = blockIdx.x * 128;

    #pragma unroll 1
    for (int ch = 0; ch < 4; ch++) {
        char* bh = smem + B_OFF + ch * 32768;
        char* bl = bh + 16384;
        #pragma unroll
        for (int j = 0; j < 8; j++) {
            int u = tid + j * 256;
            int r = u >> 4, kq = (u & 15) * 4;
            u32 off = toff(r, kq * 2);
            *(uint2*)(bh + off) = *(const uint2*)&g_W1hi[r * IN_DIM + ch * 64 + kq];
            *(uint2*)(bl + off) = *(const uint2*)&g_W1lo[r * IN_DIM + ch * 64 + kq];
        }
    }

    float4 ra[8];
    #pragma unroll
    for (int j = 0; j < 8; j++) {
        int u = tid + j * 256;
        int r = u >> 4, kq = (u & 15) * 4;
        int row = m0 + r;
        ra[j] = (row < n) ? *(const float4*)&x[(size_t)row * IN_DIM + kq]
                          : make_float4(0.f, 0.f, 0.f, 0.f);
    }

    float acc[2][8][4] = {};

    u32 PA[2], XA[2];
    #pragma unroll
    for (int mb = 0; mb < 2; mb++) {
        int r = wm * 32 + mb * 16 + (l & 7) + 8 * ((l >> 3) & 1);
        PA[mb] = (u32)((r >> 3) * 1024 + (r & 7) * 128);
        XA[mb] = (u32)((r & 7) << 4);
    }
    u32 cblA = 16 * (l >> 4);
    u32 PB[4], XB[4];
    #pragma unroll
    for (int nb = 0; nb < 4; nb++) {
        int r = wn * 64 + nb * 16 + (l & 7) + 8 * ((l >> 4) & 1);
        PB[nb] = (u32)((r >> 3) * 1024 + (r & 7) * 128);
        XB[nb] = (u32)((r & 7) << 4);
    }
    u32 cblB = 16 * ((l >> 3) & 1);

    #pragma unroll 1
    for (int ch = 0; ch < 4; ch++) {
        #pragma unroll
        for (int j = 0; j < 8; j++) {
            int u = tid + j * 256;
            int r = u >> 4, kq = (u & 15) * 4;
            float4 v = ra[j];
            __nv_bfloat16 h0 = __float2bfloat16(v.x), h1b = __float2bfloat16(v.y);
            __nv_bfloat16 h2 = __float2bfloat16(v.z), h3 = __float2bfloat16(v.w);
            __nv_bfloat16 l0 = __float2bfloat16(v.x - __bfloat162float(h0));
            __nv_bfloat16 l1 = __float2bfloat16(v.y - __bfloat162float(h1b));
            __nv_bfloat16 l2 = __float2bfloat16(v.z - __bfloat162float(h2));
            __nv_bfloat16 l3 = __float2bfloat16(v.w - __bfloat162float(h3));
            u32 off = toff(r, kq * 2);
            __nv_bfloat162 ph0 = __halves2bfloat162(h0, h1b);
            __nv_bfloat162 ph1 = __halves2bfloat162(h2, h3);
            __nv_bfloat162 pl0 = __halves2bfloat162(l0, l1);
            __nv_bfloat162 pl1 = __halves2bfloat162(l2, l3);
            *(uint2*)(smem + A_HI + off) = make_uint2(*(u32*)&ph0, *(u32*)&ph1);
            *(uint2*)(smem + A_LO + off) = make_uint2(*(u32*)&pl0, *(u32*)&pl1);
        }
        __syncthreads();

        if (ch < 3) {
            int k0 = (ch + 1) * 64;
            #pragma unroll
            for (int j = 0; j < 8; j++) {
                int u = tid + j * 256;
                int r = u >> 4, kq = (u & 15) * 4;
                int row = m0 + r;
                ra[j] = (row < n) ? *(const float4*)&x[(size_t)row * IN_DIM + k0 + kq]
                                  : make_float4(0.f, 0.f, 0.f, 0.f);
            }
        }

        u32 baseBh = sb + B_OFF + ch * 32768;
        u32 baseBl = baseBh + 16384;
        #pragma unroll
        for (int ks = 0; ks < 4; ks++) {
            u32 kb = ks * 32;
            u32 Ah[2][4], Al[2][4], Bh[4][4], Bl[4][4];
            #pragma unroll
            for (int mb = 0; mb < 2; mb++) {
                u32 aoff = PA[mb] + ((kb + cblA) ^ XA[mb]);
                ldsm4(Ah[mb], sb + A_HI + aoff);
                ldsm4(Al[mb], sb + A_LO + aoff);
            }
            #pragma unroll
            for (int nb = 0; nb < 4; nb++) {
                u32 boff = PB[nb] + ((kb + cblB) ^ XB[nb]);
                ldsm4(Bh[nb], baseBh + boff);
                ldsm4(Bl[nb], baseBl + boff);
            }
            #pragma unroll
            for (int mb = 0; mb < 2; mb++)
                #pragma unroll
                for (int nb = 0; nb < 4; nb++)
                    #pragma unroll
                    for (int j = 0; j < 2; j++) {
                        float* c = acc[mb][nb * 2 + j];
                        mma16816(c, Ah[mb], &Bh[nb][2 * j]);
                        mma16816(c, Ah[mb], &Bl[nb][2 * j]);
                        mma16816(c, Al[mb], &Bh[nb][2 * j]);
                    }
        }
        __syncthreads();
    }

    // epilogue: store UNSCALED h1 (isd applied during aggregation)
    #pragma unroll
    for (int mb = 0; mb < 2; mb++) {
        int r0 = m0 + wm * 32 + mb * 16 + (l >> 2);
        int r1 = r0 + 8;
        #pragma unroll
        for (int idx = 0; idx < 8; idx++) {
            int col = wn * 64 + idx * 8 + (l & 3) * 2;
            float* c = acc[mb][idx];
            if (r0 < n)
                *(float2*)&g_h1[(size_t)r0 * HID + col] = make_float2(c[0], c[1]);
            if (r1 < n)
                *(float2*)&g_h1[(size_t)r1 * HID + col] = make_float2(c[2], c[3]);
        }
    }
}

// ------------------------------------- fused layer1 aggregation + GEMM2 -----
// Block = 32 nodes. Phase 1: 8 warps x 4 nodes gather
//   sA[r][:] = relu(isd[d] * sum_j isd[s_j]*h1[s_j] + b1)
// Phase 2: gemm2 from smem, store h2' = (sA @ W2) * isd[row].
__global__ void __launch_bounds__(256)
k_aggemm2(const float* __restrict__ b1, const float* __restrict__ W2, int n) {
    __shared__ float sW[HID * OUT_DIM];  // 20 KB
    __shared__ float sA[32][129];        // 16.5 KB
    int tid = threadIdx.x;
    int m0 = blockIdx.x * 32;
    int w = tid >> 5, lane = tid & 31;

    for (int i = tid; i < HID * OUT_DIM; i += 256) sW[i] = W2[i];

    const float4* h1 = (const float4*)g_h1;
    float4 bb = ((const float4*)b1)[lane];
    #pragma unroll 1
    for (int i = 0; i < 4; i++) {
        int r = w * 4 + i;
        int node = m0 + r;
        float4 acc = make_float4(0.f, 0.f, 0.f, 0.f);
        float sd = 0.f;
        if (node < n) {
            int beg = g_rowstart[node];
            int end = g_rowstart[node + 1];
            int j = beg;
            for (; j + 4 <= end; j += 4) {
                int s0 = g_elist[j], s1 = g_elist[j + 1];
                int s2 = g_elist[j + 2], s3 = g_elist[j + 3];
                float q0 = __ldg(&g_isd[s0]), q1 = __ldg(&g_isd[s1]);
                float q2 = __ldg(&g_isd[s2]), q3 = __ldg(&g_isd[s3]);
                float4 v0 = h1[(size_t)s0 * 32 + lane];
                float4 v1 = h1[(size_t)s1 * 32 + lane];
                float4 v2 = h1[(size_t)s2 * 32 + lane];
                float4 v3 = h1[(size_t)s3 * 32 + lane];
                acc.x += q0 * v0.x + q1 * v1.x + q2 * v2.x + q3 * v3.x;
                acc.y += q0 * v0.y + q1 * v1.y + q2 * v2.y + q3 * v3.y;
                acc.z += q0 * v0.z + q1 * v1.z + q2 * v2.z + q3 * v3.z;
                acc.w += q0 * v0.w + q1 * v1.w + q2 * v2.w + q3 * v3.w;
            }
            for (; j < end; j++) {
                int s = g_elist[j];
                float q = __ldg(&g_isd[s]);
                float4 v = h1[(size_t)s * 32 + lane];
                acc.x += q * v.x; acc.y += q * v.y;
                acc.z += q * v.z; acc.w += q * v.w;
            }
            sd = g_isd[node];
        }
        sA[r][lane * 4 + 0] = fmaxf(fmaf(sd, acc.x, bb.x), 0.f);
        sA[r][lane * 4 + 1] = fmaxf(fmaf(sd, acc.y, bb.y), 0.f);
        sA[r][lane * 4 + 2] = fmaxf(fmaf(sd, acc.z, bb.z), 0.f);
        sA[r][lane * 4 + 3] = fmaxf(fmaf(sd, acc.w, bb.w), 0.f);
    }
    __syncthreads();

    int m = tid & 31, g = tid >> 5;
    float acc2[5] = {};
    #pragma unroll 8
    for (int k = 0; k < HID; k++) {
        float a = sA[m][k];
        #pragma unroll
        for (int j = 0; j < 5; j++)
            acc2[j] = fmaf(a, sW[k * OUT_DIM + g * 5 + j], acc2[j]);
    }
    int row = m0 + m;
    if (row < n) {
        float s = g_isd[row];
        #pragma unroll
        for (int j = 0; j < 5; j++)
            g_h2[(size_t)row * OUT_DIM + g * 5 + j] = acc2[j] * s;
    }
}

// -------------------------------------------------- layer2 CSR aggregation --
__global__ void k_agg2(const float* __restrict__ b2, float* __restrict__ out, int n) {
    int i = blockIdx.x * blockDim.x + threadIdx.x;
    if (i >= n * 10) return;
    int node = i / 10;
    int c = i - node * 10;
    int beg = g_rowstart[node];
    int end = g_rowstart[node + 1];
    const float4* h2 = (const float4*)g_h2;
    float4 acc = make_float4(0.f, 0.f, 0.f, 0.f);
    int j = beg;
    for (; j + 4 <= end; j += 4) {
        int s0 = g_elist[j], s1 = g_elist[j + 1];
        int s2 = g_elist[j + 2], s3 = g_elist[j + 3];
        float4 v0 = h2[(size_t)s0 * 10 + c];
        float4 v1 = h2[(size_t)s1 * 10 + c];
        float4 v2 = h2[(size_t)s2 * 10 + c];
        float4 v3 = h2[(size_t)s3 * 10 + c];
        acc.x += v0.x + v1.x + v2.x + v3.x;
        acc.y += v0.y + v1.y + v2.y + v3.y;
        acc.z += v0.z + v1.z + v2.z + v3.z;
        acc.w += v0.w + v1.w + v2.w + v3.w;
    }
    for (; j < end; j++) {
        int s = g_elist[j];
        float4 v = h2[(size_t)s * 10 + c];
        acc.x += v.x; acc.y += v.y; acc.z += v.z; acc.w += v.w;
    }
    float sd = g_isd[node];
    float4 bb = ((const float4*)b2)[c];
    ((float4*)out)[i] = make_float4(fmaf(sd, acc.x, bb.x), fmaf(sd, acc.y, bb.y),
                                    fmaf(sd, acc.z, bb.z), fmaf(sd, acc.w, bb.w));
}

// ---------------------------------------------------------------- launch ----
extern "C" void kernel_launch(void* const* d_in, const int* in_sizes, int n_in,
                              void* d_out, int out_size) {
    const float* x   = (const float*)d_in[0];
    const int*   src = (const int*)d_in[1];
    const int*   dst = (const int*)d_in[2];
    const float* W1  = (const float*)d_in[3];
    const float* b1  = (const float*)d_in[4];
    const float* W2  = (const float*)d_in[5];
    const float* b2  = (const float*)d_in[6];
    float* out = (float*)d_out;

    int n = in_sizes[0] / IN_DIM;
    int e = in_sizes[1];

    static cudaStream_t s_side = 0;
    static cudaEvent_t e_fork = 0, e_join = 0;
    if (!s_side) {
        cudaFuncSetAttribute(k_gemm1, cudaFuncAttributeMaxDynamicSharedMemorySize,
                             SMEM_G1);
        cudaStreamCreateWithFlags(&s_side, cudaStreamNonBlocking);
        cudaEventCreateWithFlags(&e_fork, cudaEventDisableTiming);
        cudaEventCreateWithFlags(&e_join, cudaEventDisableTiming);
    }

    // fork: CSR/degree chain on side stream, independent of gemm1 chain
    cudaEventRecord(e_fork, 0);
    cudaStreamWaitEvent(s_side, e_fork, 0);

    k_zero_deg<<<(n + 255) / 256, 256, 0, s_side>>>(n);
    k_count<<<(e + 255) / 256, 256, 0, s_side>>>(dst, e);
    k_isd<<<(n + 255) / 256, 256, 0, s_side>>>(n);
    k_scan1<<<NB_SCAN, SCAN_BS, 0, s_side>>>(n);
    k_scan2<<<1, 32, 0, s_side>>>(n, e);
    k_scan3<<<(n + 255) / 256, 256, 0, s_side>>>(n);
    k_scatter<<<(e + 255) / 256, 256, 0, s_side>>>(src, dst, e);
    cudaEventRecord(e_join, s_side);

    // main stream: weight prep + gemm1 (no isd dependency)
    k_splitW1<<<(HID * IN_DIM + 255) / 256, 256>>>(W1);
    k_gemm1<<<(n + 127) / 128, 256, SMEM_G1>>>(x, n);

    // join, then fused aggregation+gemm2 and final aggregation
    cudaStreamWaitEvent(0, e_join, 0);
    k_aggemm2<<<(n + 31) / 32, 256>>>(b1, W2, n);
    k_agg2<<<(n * 10 + 255) / 256, 256>>>(b2, out, n);
}

// round 8
// speedup vs baseline: 2.0294x; 1.0129x over previous
#include <cuda_runtime.h>
#include <cuda_bf16.h>

#define N_NODES 100000
#define N_EDGES 1600000
#define IN_DIM  256
#define HID     128
#define OUT_DIM 40
#define SCAN_BS 1024
#define NB_SCAN ((N_NODES + SCAN_BS - 1) / SCAN_BS)

typedef unsigned long long u64;
typedef unsigned int u32;

// ---- scratch ----
__device__ float g_deg[N_NODES];
__device__ float g_isd[N_NODES];
__device__ float g_h1[(size_t)N_NODES * HID];     // UNSCALED x@W1
__device__ float g_h2[(size_t)N_NODES * OUT_DIM];
__device__ __align__(16) __nv_bfloat16 g_W1hi[HID * IN_DIM];
__device__ __align__(16) __nv_bfloat16 g_W1lo[HID * IN_DIM];
__device__ int g_rowstart[N_NODES + 1];
__device__ int g_cursor[N_NODES];
__device__ int g_bsum[NB_SCAN];
__device__ int g_elist[N_EDGES];

// ---------------------------------------------------------------- degree ----
__global__ void k_zero_deg(int n) {
    int i = blockIdx.x * blockDim.x + threadIdx.x;
    if (i < n) g_deg[i] = 0.f;
}
__global__ void k_count(const int* __restrict__ dst, int e) {
    int i = blockIdx.x * blockDim.x + threadIdx.x;
    if (i < e) atomicAdd(&g_deg[dst[i]], 1.0f);
}
__global__ void k_isd(int n) {
    int i = blockIdx.x * blockDim.x + threadIdx.x;
    if (i < n) {
        float d = g_deg[i];
        g_isd[i] = (d > 0.f) ? rsqrtf(d) : 0.f;
    }
}

// ----------------------------------------------------------- CSR build ------
__global__ void k_scan1(int n) {
    __shared__ int sm[SCAN_BS];
    int t = threadIdx.x;
    int idx = blockIdx.x * SCAN_BS + t;
    int v = (idx < n) ? (int)g_deg[idx] : 0;
    sm[t] = v;
    __syncthreads();
    #pragma unroll
    for (int off = 1; off < SCAN_BS; off <<= 1) {
        int y = (t >= off) ? sm[t - off] : 0;
        __syncthreads();
        sm[t] += y;
        __syncthreads();
    }
    if (idx < n) g_rowstart[idx] = sm[t] - v;
    if (t == SCAN_BS - 1) g_bsum[blockIdx.x] = sm[t];
}
__global__ void k_scan2(int n, int e) {
    if (threadIdx.x == 0) {
        int run = 0;
        for (int i = 0; i < NB_SCAN; i++) {
            int t = g_bsum[i];
            g_bsum[i] = run;
            run += t;
        }
        g_rowstart[n] = run;
    }
}
__global__ void k_scan3(int n) {
    int i = blockIdx.x * blockDim.x + threadIdx.x;
    if (i < n) {
        int rs = g_rowstart[i] + g_bsum[i >> 10];
        g_rowstart[i] = rs;
        g_cursor[i] = rs;
    }
}
__global__ void k_scatter(const int* __restrict__ src, const int* __restrict__ dst, int e) {
    int i = blockIdx.x * blockDim.x + threadIdx.x;
    if (i < e) {
        int pos = atomicAdd(&g_cursor[dst[i]], 1);
        g_elist[pos] = src[i];
    }
}

// ------------------------------------------------- W1 -> bf16 hi/lo [n][k] --
__global__ void k_splitW1(const float* __restrict__ W1) {
    int i = blockIdx.x * blockDim.x + threadIdx.x;
    if (i >= HID * IN_DIM) return;
    int n = i & (HID - 1), k = i >> 7;
    float v = W1[(size_t)k * HID + n];
    __nv_bfloat16 hi = __float2bfloat16(v);
    __nv_bfloat16 lo = __float2bfloat16(v - __bfloat162float(hi));
    g_W1hi[n * IN_DIM + k] = hi;
    g_W1lo[n * IN_DIM + k] = lo;
}

// -------------------------------------------------------------- HMMA GEMM1 --
// BM=64, BN=128, K chunks of 64, double-buffered smem, 2 CTAs/SM.
#define A_HI   0
#define A_LO   8192
#define B_HI   16384
#define B_LO   32768
#define AB_STRIDE 49152
#define SMEM_G1 (2 * AB_STRIDE)   // 96 KB

__device__ __forceinline__ u32 toff(int r, int cb) {
    return (u32)((r >> 3) * 1024 + (r & 7) * 128 + (cb ^ ((r & 7) << 4)));
}
__device__ __forceinline__ void ldsm4(u32* r, u32 addr) {
    asm volatile("ldmatrix.sync.aligned.m8n8.x4.shared.b16 {%0,%1,%2,%3}, [%4];"
                 : "=r"(r[0]), "=r"(r[1]), "=r"(r[2]), "=r"(r[3]) : "r"(addr));
}
__device__ __forceinline__ void mma16816(float* c, const u32* a, const u32* b) {
    asm volatile(
        "mma.sync.aligned.m16n8k16.row.col.f32.bf16.bf16.f32 "
        "{%0,%1,%2,%3}, {%4,%5,%6,%7}, {%8,%9}, {%0,%1,%2,%3};"
        : "+f"(c[0]), "+f"(c[1]), "+f"(c[2]), "+f"(c[3])
        : "r"(a[0]), "r"(a[1]), "r"(a[2]), "r"(a[3]), "r"(b[0]), "r"(b[1]));
}

__global__ void __launch_bounds__(256, 2)
k_gemm1(const float* __restrict__ x, int n) {
    extern __shared__ char smem[];
    u32 sb;
    asm("{ .reg .u64 t; cvta.to.shared.u64 t, %1; cvt.u32.u64 %0, t; }"
        : "=r"(sb) : "l"(smem));
    const int tid = threadIdx.x;
    const int l = tid & 31;
    const int wid = tid >> 5;
    const int wm = wid & 1;        // 2 warps over M (32 rows each)
    const int wn = wid >> 1;       // 4 warps over N (32 cols each)
    const int m0 = blockIdx.x * 64;

    float4 ra[4];
    uint4 rbh[4], rbl[4];

    // prefetch chunk 0
    #pragma unroll
    for (int j = 0; j < 4; j++) {
        int u = tid + j * 256;
        int r = u >> 4, kq = (u & 15) * 4;
        int row = m0 + r;
        ra[j] = (row < n) ? *(const float4*)&x[(size_t)row * IN_DIM + kq]
                          : make_float4(0.f, 0.f, 0.f, 0.f);
    }
    #pragma unroll
    for (int j = 0; j < 4; j++) {
        int u = tid + j * 256;
        int r = u >> 3, kq = (u & 7) * 8;
        rbh[j] = *(const uint4*)&g_W1hi[r * IN_DIM + kq];
        rbl[j] = *(const uint4*)&g_W1lo[r * IN_DIM + kq];
    }

    // stage chunk 0 into buf 0
    #pragma unroll
    for (int j = 0; j < 4; j++) {
        int u = tid + j * 256;
        int r = u >> 4, kq = (u & 15) * 4;
        float4 v = ra[j];
        __nv_bfloat16 h0 = __float2bfloat16(v.x), h1b = __float2bfloat16(v.y);
        __nv_bfloat16 h2 = __float2bfloat16(v.z), h3 = __float2bfloat16(v.w);
        __nv_bfloat16 l0 = __float2bfloat16(v.x - __bfloat162float(h0));
        __nv_bfloat16 l1 = __float2bfloat16(v.y - __bfloat162float(h1b));
        __nv_bfloat16 l2 = __float2bfloat16(v.z - __bfloat162float(h2));
        __nv_bfloat16 l3 = __float2bfloat16(v.w - __bfloat162float(h3));
        u32 off = toff(r, kq * 2);
        __nv_bfloat162 ph0 = __halves2bfloat162(h0, h1b);
        __nv_bfloat162 ph1 = __halves2bfloat162(h2, h3);
        __nv_bfloat162 pl0 = __halves2bfloat162(l0, l1);
        __nv_bfloat162 pl1 = __halves2bfloat162(l2, l3);
        *(uint2*)(smem + A_HI + off) = make_uint2(*(u32*)&ph0, *(u32*)&ph1);
        *(uint2*)(smem + A_LO + off) = make_uint2(*(u32*)&pl0, *(u32*)&pl1);
    }
    #pragma unroll
    for (int j = 0; j < 4; j++) {
        int u = tid + j * 256;
        int r = u >> 3, kq = (u & 7) * 8;
        u32 off = toff(r, kq * 2);
        *(uint4*)(smem + B_HI + off) = rbh[j];
        *(uint4*)(smem + B_LO + off) = rbl[j];
    }
    __syncthreads();

    float acc[2][4][4] = {};

    u32 PA[2], XA[2];
    #pragma unroll
    for (int mb = 0; mb < 2; mb++) {
        int r = wm * 32 + mb * 16 + (l & 7) + 8 * ((l >> 3) & 1);
        PA[mb] = (u32)((r >> 3) * 1024 + (r & 7) * 128);
        XA[mb] = (u32)((r & 7) << 4);
    }
    u32 cblA = 16 * (l >> 4);
    u32 PB[2], XB[2];
    #pragma unroll
    for (int nb = 0; nb < 2; nb++) {
        int r = wn * 32 + nb * 16 + (l & 7) + 8 * ((l >> 4) & 1);
        PB[nb] = (u32)((r >> 3) * 1024 + (r & 7) * 128);
        XB[nb] = (u32)((r & 7) << 4);
    }
    u32 cblB = 16 * ((l >> 3) & 1);

    #pragma unroll 1
    for (int ch = 0; ch < 4; ch++) {
        u32 base = sb + (u32)(ch & 1) * AB_STRIDE;

        // prefetch next chunk into regs
        if (ch < 3) {
            int k0 = (ch + 1) * 64;
            #pragma unroll
            for (int j = 0; j < 4; j++) {
                int u = tid + j * 256;
                int r = u >> 4, kq = (u & 15) * 4;
                int row = m0 + r;
                ra[j] = (row < n) ? *(const float4*)&x[(size_t)row * IN_DIM + k0 + kq]
                                  : make_float4(0.f, 0.f, 0.f, 0.f);
            }
            #pragma unroll
            for (int j = 0; j < 4; j++) {
                int u = tid + j * 256;
                int r = u >> 3, kq = (u & 7) * 8;
                rbh[j] = *(const uint4*)&g_W1hi[r * IN_DIM + k0 + kq];
                rbl[j] = *(const uint4*)&g_W1lo[r * IN_DIM + k0 + kq];
            }
        }

        // MMA on current buffer
        #pragma unroll
        for (int ks = 0; ks < 4; ks++) {
            u32 kb = ks * 32;
            u32 Ah[2][4], Al[2][4], Bh[2][4], Bl[2][4];
            #pragma unroll
            for (int mb = 0; mb < 2; mb++) {
                u32 aoff = PA[mb] + ((kb + cblA) ^ XA[mb]);
                ldsm4(Ah[mb], base + A_HI + aoff);
                ldsm4(Al[mb], base + A_LO + aoff);
            }
            #pragma unroll
            for (int nb = 0; nb < 2; nb++) {
                u32 boff = PB[nb] + ((kb + cblB) ^ XB[nb]);
                ldsm4(Bh[nb], base + B_HI + boff);
                ldsm4(Bl[nb], base + B_LO + boff);
            }
            #pragma unroll
            for (int mb = 0; mb < 2; mb++)
                #pragma unroll
                for (int nb = 0; nb < 2; nb++)
                    #pragma unroll
                    for (int j = 0; j < 2; j++) {
                        float* c = acc[mb][nb * 2 + j];
                        mma16816(c, Ah[mb], &Bh[nb][2 * j]);
                        mma16816(c, Ah[mb], &Bl[nb][2 * j]);
                        mma16816(c, Al[mb], &Bh[nb][2 * j]);
                    }
        }

        // stage prefetched chunk into other buffer
        if (ch < 3) {
            char* nb_ = smem + ((ch + 1) & 1) * AB_STRIDE;
            #pragma unroll
            for (int j = 0; j < 4; j++) {
                int u = tid + j * 256;
                int r = u >> 4, kq = (u & 15) * 4;
                float4 v = ra[j];
                __nv_bfloat16 h0 = __float2bfloat16(v.x), h1b = __float2bfloat16(v.y);
                __nv_bfloat16 h2 = __float2bfloat16(v.z), h3 = __float2bfloat16(v.w);
                __nv_bfloat16 l0 = __float2bfloat16(v.x - __bfloat162float(h0));
                __nv_bfloat16 l1 = __float2bfloat16(v.y - __bfloat162float(h1b));
                __nv_bfloat16 l2 = __float2bfloat16(v.z - __bfloat162float(h2));
                __nv_bfloat16 l3 = __float2bfloat16(v.w - __bfloat162float(h3));
                u32 off = toff(r, kq * 2);
                __nv_bfloat162 ph0 = __halves2bfloat162(h0, h1b);
                __nv_bfloat162 ph1 = __halves2bfloat162(h2, h3);
                __nv_bfloat162 pl0 = __halves2bfloat162(l0, l1);
                __nv_bfloat162 pl1 = __halves2bfloat162(l2, l3);
                *(uint2*)(nb_ + A_HI + off) = make_uint2(*(u32*)&ph0, *(u32*)&ph1);
                *(uint2*)(nb_ + A_LO + off) = make_uint2(*(u32*)&pl0, *(u32*)&pl1);
            }
            #pragma unroll
            for (int j = 0; j < 4; j++) {
                int u = tid + j * 256;
                int r = u >> 3, kq = (u & 7) * 8;
                u32 off = toff(r, kq * 2);
                *(uint4*)(nb_ + B_HI + off) = rbh[j];
                *(uint4*)(nb_ + B_LO + off) = rbl[j];
            }
            __syncthreads();
        }
    }

    // epilogue: store UNSCALED h1
    #pragma unroll
    for (int mb = 0; mb < 2; mb++) {
        int r0 = m0 + wm * 32 + mb * 16 + (l >> 2);
        int r1 = r0 + 8;
        #pragma unroll
        for (int idx = 0; idx < 4; idx++) {
            int col = wn * 32 + idx * 8 + (l & 3) * 2;
            float* c = acc[mb][idx];
            if (r0 < n)
                *(float2*)&g_h1[(size_t)r0 * HID + col] = make_float2(c[0], c[1]);
            if (r1 < n)
                *(float2*)&g_h1[(size_t)r1 * HID + col] = make_float2(c[2], c[3]);
        }
    }
}

// ------------------------------------- fused layer1 aggregation + GEMM2 -----
__global__ void __launch_bounds__(256)
k_aggemm2(const float* __restrict__ b1, const float* __restrict__ W2, int n) {
    __shared__ float sW[HID * OUT_DIM];
    __shared__ float sA[32][129];
    int tid = threadIdx.x;
    int m0 = blockIdx.x * 32;
    int w = tid >> 5, lane = tid & 31;

    for (int i = tid; i < HID * OUT_DIM; i += 256) sW[i] = W2[i];

    const float4* h1 = (const float4*)g_h1;
    float4 bb = ((const float4*)b1)[lane];
    #pragma unroll 1
    for (int i = 0; i < 4; i++) {
        int r = w * 4 + i;
        int node = m0 + r;
        float4 acc = make_float4(0.f, 0.f, 0.f, 0.f);
        float sd = 0.f;
        if (node < n) {
            int beg = g_rowstart[node];
            int end = g_rowstart[node + 1];
            int j = beg;
            for (; j + 4 <= end; j += 4) {
                int s0 = g_elist[j], s1 = g_elist[j + 1];
                int s2 = g_elist[j + 2], s3 = g_elist[j + 3];
                float q0 = __ldg(&g_isd[s0]), q1 = __ldg(&g_isd[s1]);
                float q2 = __ldg(&g_isd[s2]), q3 = __ldg(&g_isd[s3]);
                float4 v0 = h1[(size_t)s0 * 32 + lane];
                float4 v1 = h1[(size_t)s1 * 32 + lane];
                float4 v2 = h1[(size_t)s2 * 32 + lane];
                float4 v3 = h1[(size_t)s3 * 32 + lane];
                acc.x += q0 * v0.x + q1 * v1.x + q2 * v2.x + q3 * v3.x;
                acc.y += q0 * v0.y + q1 * v1.y + q2 * v2.y + q3 * v3.y;
                acc.z += q0 * v0.z + q1 * v1.z + q2 * v2.z + q3 * v3.z;
                acc.w += q0 * v0.w + q1 * v1.w + q2 * v2.w + q3 * v3.w;
            }
            for (; j < end; j++) {
                int s = g_elist[j];
                float q = __ldg(&g_isd[s]);
                float4 v = h1[(size_t)s * 32 + lane];
                acc.x += q * v.x; acc.y += q * v.y;
                acc.z += q * v.z; acc.w += q * v.w;
            }
            sd = g_isd[node];
        }
        sA[r][lane * 4 + 0] = fmaxf(fmaf(sd, acc.x, bb.x), 0.f);
        sA[r][lane * 4 + 1] = fmaxf(fmaf(sd, acc.y, bb.y), 0.f);
        sA[r][lane * 4 + 2] = fmaxf(fmaf(sd, acc.z, bb.z), 0.f);
        sA[r][lane * 4 + 3] = fmaxf(fmaf(sd, acc.w, bb.w), 0.f);
    }
    __syncthreads();

    int m = tid & 31, g = tid >> 5;
    float acc2[5] = {};
    #pragma unroll 8
    for (int k = 0; k < HID; k++) {
        float a = sA[m][k];
        #pragma unroll
        for (int j = 0; j < 5; j++)
            acc2[j] = fmaf(a, sW[k * OUT_DIM + g * 5 + j], acc2[j]);
    }
    int row = m0 + m;
    if (row < n) {
        float s = g_isd[row];
        #pragma unroll
        for (int j = 0; j < 5; j++)
            g_h2[(size_t)row * OUT_DIM + g * 5 + j] = acc2[j] * s;
    }
}

// -------------------------------------------------- layer2 CSR aggregation --
__global__ void k_agg2(const float* __restrict__ b2, float* __restrict__ out, int n) {
    int i = blockIdx.x * blockDim.x + threadIdx.x;
    if (i >= n * 10) return;
    int node = i / 10;
    int c = i - node * 10;
    int beg = g_rowstart[node];
    int end = g_rowstart[node + 1];
    const float4* h2 = (const float4*)g_h2;
    float4 acc = make_float4(0.f, 0.f, 0.f, 0.f);
    int j = beg;
    for (; j + 4 <= end; j += 4) {
        int s0 = g_elist[j], s1 = g_elist[j + 1];
        int s2 = g_elist[j + 2], s3 = g_elist[j + 3];
        float4 v0 = h2[(size_t)s0 * 10 + c];
        float4 v1 = h2[(size_t)s1 * 10 + c];
        float4 v2 = h2[(size_t)s2 * 10 + c];
        float4 v3 = h2[(size_t)s3 * 10 + c];
        acc.x += v0.x + v1.x + v2.x + v3.x;
        acc.y += v0.y + v1.y + v2.y + v3.y;
        acc.z += v0.z + v1.z + v2.z + v3.z;
        acc.w += v0.w + v1.w + v2.w + v3.w;
    }
    for (; j < end; j++) {
        int s = g_elist[j];
        float4 v = h2[(size_t)s * 10 + c];
        acc.x += v.x; acc.y += v.y; acc.z += v.z; acc.w += v.w;
    }
    float sd = g_isd[node];
    float4 bb = ((const float4*)b2)[c];
    ((float4*)out)[i] = make_float4(fmaf(sd, acc.x, bb.x), fmaf(sd, acc.y, bb.y),
                                    fmaf(sd, acc.z, bb.z), fmaf(sd, acc.w, bb.w));
}

// ---------------------------------------------------------------- launch ----
extern "C" void kernel_launch(void* const* d_in, const int* in_sizes, int n_in,
                              void* d_out, int out_size) {
    const float* x   = (const float*)d_in[0];
    const int*   src = (const int*)d_in[1];
    const int*   dst = (const int*)d_in[2];
    const float* W1  = (const float*)d_in[3];
    const float* b1  = (const float*)d_in[4];
    const float* W2  = (const float*)d_in[5];
    const float* b2  = (const float*)d_in[6];
    float* out = (float*)d_out;

    int n = in_sizes[0] / IN_DIM;
    int e = in_sizes[1];

    static cudaStream_t s_side = 0;
    static cudaEvent_t e_fork = 0, e_join = 0;
    if (!s_side) {
        cudaFuncSetAttribute(k_gemm1, cudaFuncAttributeMaxDynamicSharedMemorySize,
                             SMEM_G1);
        cudaStreamCreateWithFlags(&s_side, cudaStreamNonBlocking);
        cudaEventCreateWithFlags(&e_fork, cudaEventDisableTiming);
        cudaEventCreateWithFlags(&e_join, cudaEventDisableTiming);
    }

    cudaEventRecord(e_fork, 0);
    cudaStreamWaitEvent(s_side, e_fork, 0);

    k_zero_deg<<<(n + 255) / 256, 256, 0, s_side>>>(n);
    k_count<<<(e + 255) / 256, 256, 0, s_side>>>(dst, e);
    k_isd<<<(n + 255) / 256, 256, 0, s_side>>>(n);
    k_scan1<<<NB_SCAN, SCAN_BS, 0, s_side>>>(n);
    k_scan2<<<1, 32, 0, s_side>>>(n, e);
    k_scan3<<<(n + 255) / 256, 256, 0, s_side>>>(n);
    k_scatter<<<(e + 255) / 256, 256, 0, s_side>>>(src, dst, e);
    cudaEventRecord(e_join, s_side);

    k_splitW1<<<(HID * IN_DIM + 255) / 256, 256>>>(W1);
    k_gemm1<<<(n + 63) / 64, 256, SMEM_G1>>>(x, n);

    cudaStreamWaitEvent(0, e_join, 0);
    k_aggemm2<<<(n + 31) / 32, 256>>>(b1, W2, n);
    k_agg2<<<(n * 10 + 255) / 256, 256>>>(b2, out, n);
}

// round 9
// speedup vs baseline: 2.1959x; 1.0821x over previous
#include <cuda_runtime.h>
#include <cuda_fp16.h>

#define N_NODES 100000
#define N_EDGES 1600000
#define IN_DIM  256
#define HID     128
#define OUT_DIM 40
#define SCAN_BS 1024
#define NB_SCAN ((N_NODES + SCAN_BS - 1) / SCAN_BS)

typedef unsigned long long u64;
typedef unsigned int u32;

// ---- scratch ----
__device__ float g_deg[N_NODES];
__device__ float g_isd[N_NODES];
__device__ float g_h1[(size_t)N_NODES * HID];     // UNSCALED x@W1
__device__ float g_h2[(size_t)N_NODES * OUT_DIM];
__device__ __align__(16) __half g_W1h[HID * IN_DIM];  // fp16(W1), [n][k]
__device__ int g_rowstart[N_NODES + 1];
__device__ int g_cursor[N_NODES];
__device__ int g_bsum[NB_SCAN];
__device__ int g_elist[N_EDGES];

// ---------------------------------------------------------------- degree ----
__global__ void k_zero_deg(int n) {
    int i = blockIdx.x * blockDim.x + threadIdx.x;
    if (i < n) g_deg[i] = 0.f;
}
__global__ void k_count(const int* __restrict__ dst, int e) {
    int i = blockIdx.x * blockDim.x + threadIdx.x;
    if (i < e) atomicAdd(&g_deg[dst[i]], 1.0f);
}
__global__ void k_isd(int n) {
    int i = blockIdx.x * blockDim.x + threadIdx.x;
    if (i < n) {
        float d = g_deg[i];
        g_isd[i] = (d > 0.f) ? rsqrtf(d) : 0.f;
    }
}

// ----------------------------------------------------------- CSR build ------
__global__ void k_scan1(int n) {
    __shared__ int sm[SCAN_BS];
    int t = threadIdx.x;
    int idx = blockIdx.x * SCAN_BS + t;
    int v = (idx < n) ? (int)g_deg[idx] : 0;
    sm[t] = v;
    __syncthreads();
    #pragma unroll
    for (int off = 1; off < SCAN_BS; off <<= 1) {
        int y = (t >= off) ? sm[t - off] : 0;
        __syncthreads();
        sm[t] += y;
        __syncthreads();
    }
    if (idx < n) g_rowstart[idx] = sm[t] - v;
    if (t == SCAN_BS - 1) g_bsum[blockIdx.x] = sm[t];
}
__global__ void k_scan2(int n, int e) {
    if (threadIdx.x == 0) {
        int run = 0;
        for (int i = 0; i < NB_SCAN; i++) {
            int t = g_bsum[i];
            g_bsum[i] = run;
            run += t;
        }
        g_rowstart[n] = run;
    }
}
__global__ void k_scan3(int n) {
    int i = blockIdx.x * blockDim.x + threadIdx.x;
    if (i < n) {
        int rs = g_rowstart[i] + g_bsum[i >> 10];
        g_rowstart[i] = rs;
        g_cursor[i] = rs;
    }
}
__global__ void k_scatter(const int* __restrict__ src, const int* __restrict__ dst, int e) {
    int i = blockIdx.x * blockDim.x + threadIdx.x;
    if (i < e) {
        int pos = atomicAdd(&g_cursor[dst[i]], 1);
        g_elist[pos] = src[i];
    }
}

// --------------------------------------------------- W1 -> fp16 [n][k] ------
__global__ void k_splitW1(const float* __restrict__ W1) {
    int i = blockIdx.x * blockDim.x + threadIdx.x;
    if (i >= HID * IN_DIM) return;
    int n = i & (HID - 1), k = i >> 7;
    g_W1h[n * IN_DIM + k] = __float2half(W1[(size_t)k * HID + n]);
}

// -------------------------------------------------------------- HMMA GEMM1 --
// h1 = x @ W1 via 2-pass fp16 split: D = Ahi*Bh + Alo*Bh  (Blo term dropped,
// rel err ~1e-4). BM=64, BN=128, K chunks of 64, double-buffered, 2 CTAs/SM.
#define A_HI   0
#define A_LO   8192
#define B_H    16384
#define AB_STRIDE 32768
#define SMEM_G1 (2 * AB_STRIDE)   // 64 KB

__device__ __forceinline__ u32 toff(int r, int cb) {
    return (u32)((r >> 3) * 1024 + (r & 7) * 128 + (cb ^ ((r & 7) << 4)));
}
__device__ __forceinline__ void ldsm4(u32* r, u32 addr) {
    asm volatile("ldmatrix.sync.aligned.m8n8.x4.shared.b16 {%0,%1,%2,%3}, [%4];"
                 : "=r"(r[0]), "=r"(r[1]), "=r"(r[2]), "=r"(r[3]) : "r"(addr));
}
__device__ __forceinline__ void mma16816(float* c, const u32* a, const u32* b) {
    asm volatile(
        "mma.sync.aligned.m16n8k16.row.col.f32.f16.f16.f32 "
        "{%0,%1,%2,%3}, {%4,%5,%6,%7}, {%8,%9}, {%0,%1,%2,%3};"
        : "+f"(c[0]), "+f"(c[1]), "+f"(c[2]), "+f"(c[3])
        : "r"(a[0]), "r"(a[1]), "r"(a[2]), "r"(a[3]), "r"(b[0]), "r"(b[1]));
}

__global__ void __launch_bounds__(256, 2)
k_gemm1(const float* __restrict__ x, int n) {
    extern __shared__ char smem[];
    u32 sb;
    asm("{ .reg .u64 t; cvta.to.shared.u64 t, %1; cvt.u32.u64 %0, t; }"
        : "=r"(sb) : "l"(smem));
    const int tid = threadIdx.x;
    const int l = tid & 31;
    const int wid = tid >> 5;
    const int wm = wid & 1;
    const int wn = wid >> 1;
    const int m0 = blockIdx.x * 64;

    float4 ra[4];
    uint4 rbh[4];

    #pragma unroll
    for (int j = 0; j < 4; j++) {
        int u = tid + j * 256;
        int r = u >> 4, kq = (u & 15) * 4;
        int row = m0 + r;
        ra[j] = (row < n) ? *(const float4*)&x[(size_t)row * IN_DIM + kq]
                          : make_float4(0.f, 0.f, 0.f, 0.f);
    }
    #pragma unroll
    for (int j = 0; j < 4; j++) {
        int u = tid + j * 256;
        int r = u >> 3, kq = (u & 7) * 8;
        rbh[j] = *(const uint4*)&g_W1h[r * IN_DIM + kq];
    }

    #pragma unroll
    for (int j = 0; j < 4; j++) {
        int u = tid + j * 256;
        int r = u >> 4, kq = (u & 15) * 4;
        float4 v = ra[j];
        __half h0 = __float2half(v.x), h1h = __float2half(v.y);
        __half h2 = __float2half(v.z), h3 = __float2half(v.w);
        __half l0 = __float2half(v.x - __half2float(h0));
        __half l1 = __float2half(v.y - __half2float(h1h));
        __half l2 = __float2half(v.z - __half2float(h2));
        __half l3 = __float2half(v.w - __half2float(h3));
        u32 off = toff(r, kq * 2);
        __half2 ph0 = __halves2half2(h0, h1h), ph1 = __halves2half2(h2, h3);
        __half2 pl0 = __halves2half2(l0, l1), pl1 = __halves2half2(l2, l3);
        *(uint2*)(smem + A_HI + off) = make_uint2(*(u32*)&ph0, *(u32*)&ph1);
        *(uint2*)(smem + A_LO + off) = make_uint2(*(u32*)&pl0, *(u32*)&pl1);
    }
    #pragma unroll
    for (int j = 0; j < 4; j++) {
        int u = tid + j * 256;
        int r = u >> 3, kq = (u & 7) * 8;
        *(uint4*)(smem + B_H + toff(r, kq * 2)) = rbh[j];
    }
    __syncthreads();

    float acc[2][4][4] = {};

    u32 PA[2], XA[2];
    #pragma unroll
    for (int mb = 0; mb < 2; mb++) {
        int r = wm * 32 + mb * 16 + (l & 7) + 8 * ((l >> 3) & 1);
        PA[mb] = (u32)((r >> 3) * 1024 + (r & 7) * 128);
        XA[mb] = (u32)((r & 7) << 4);
    }
    u32 cblA = 16 * (l >> 4);
    u32 PB[2], XB[2];
    #pragma unroll
    for (int nb = 0; nb < 2; nb++) {
        int r = wn * 32 + nb * 16 + (l & 7) + 8 * ((l >> 4) & 1);
        PB[nb] = (u32)((r >> 3) * 1024 + (r & 7) * 128);
        XB[nb] = (u32)((r & 7) << 4);
    }
    u32 cblB = 16 * ((l >> 3) & 1);

    #pragma unroll 1
    for (int ch = 0; ch < 4; ch++) {
        u32 base = sb + (u32)(ch & 1) * AB_STRIDE;

        if (ch < 3) {
            int k0 = (ch + 1) * 64;
            #pragma unroll
            for (int j = 0; j < 4; j++) {
                int u = tid + j * 256;
                int r = u >> 4, kq = (u & 15) * 4;
                int row = m0 + r;
                ra[j] = (row < n) ? *(const float4*)&x[(size_t)row * IN_DIM + k0 + kq]
                                  : make_float4(0.f, 0.f, 0.f, 0.f);
            }
            #pragma unroll
            for (int j = 0; j < 4; j++) {
                int u = tid + j * 256;
                int r = u >> 3, kq = (u & 7) * 8;
                rbh[j] = *(const uint4*)&g_W1h[r * IN_DIM + k0 + kq];
            }
        }

        #pragma unroll
        for (int ks = 0; ks < 4; ks++) {
            u32 kb = ks * 32;
            u32 Ah[2][4], Al[2][4], Bh[2][4];
            #pragma unroll
            for (int mb = 0; mb < 2; mb++) {
                u32 aoff = PA[mb] + ((kb + cblA) ^ XA[mb]);
                ldsm4(Ah[mb], base + A_HI + aoff);
                ldsm4(Al[mb], base + A_LO + aoff);
            }
            #pragma unroll
            for (int nb = 0; nb < 2; nb++) {
                u32 boff = PB[nb] + ((kb + cblB) ^ XB[nb]);
                ldsm4(Bh[nb], base + B_H + boff);
            }
            #pragma unroll
            for (int mb = 0; mb < 2; mb++)
                #pragma unroll
                for (int nb = 0; nb < 2; nb++)
                    #pragma unroll
                    for (int j = 0; j < 2; j++) {
                        float* c = acc[mb][nb * 2 + j];
                        mma16816(c, Ah[mb], &Bh[nb][2 * j]);
                        mma16816(c, Al[mb], &Bh[nb][2 * j]);
                    }
        }

        if (ch < 3) {
            char* nb_ = smem + ((ch + 1) & 1) * AB_STRIDE;
            #pragma unroll
            for (int j = 0; j < 4; j++) {
                int u = tid + j * 256;
                int r = u >> 4, kq = (u & 15) * 4;
                float4 v = ra[j];
                __half h0 = __float2half(v.x), h1h = __float2half(v.y);
                __half h2 = __float2half(v.z), h3 = __float2half(v.w);
                __half l0 = __float2half(v.x - __half2float(h0));
                __half l1 = __float2half(v.y - __half2float(h1h));
                __half l2 = __float2half(v.z - __half2float(h2));
                __half l3 = __float2half(v.w - __half2float(h3));
                u32 off = toff(r, kq * 2);
                __half2 ph0 = __halves2half2(h0, h1h), ph1 = __halves2half2(h2, h3);
                __half2 pl0 = __halves2half2(l0, l1), pl1 = __halves2half2(l2, l3);
                *(uint2*)(nb_ + A_HI + off) = make_uint2(*(u32*)&ph0, *(u32*)&ph1);
                *(uint2*)(nb_ + A_LO + off) = make_uint2(*(u32*)&pl0, *(u32*)&pl1);
            }
            #pragma unroll
            for (int j = 0; j < 4; j++) {
                int u = tid + j * 256;
                int r = u >> 3, kq = (u & 7) * 8;
                *(uint4*)(nb_ + B_H + toff(r, kq * 2)) = rbh[j];
            }
            __syncthreads();
        }
    }

    #pragma unroll
    for (int mb = 0; mb < 2; mb++) {
        int r0 = m0 + wm * 32 + mb * 16 + (l >> 2);
        int r1 = r0 + 8;
        #pragma unroll
        for (int idx = 0; idx < 4; idx++) {
            int col = wn * 32 + idx * 8 + (l & 3) * 2;
            float* c = acc[mb][idx];
            if (r0 < n)
                *(float2*)&g_h1[(size_t)r0 * HID + col] = make_float2(c[0], c[1]);
            if (r1 < n)
                *(float2*)&g_h1[(size_t)r1 * HID + col] = make_float2(c[2], c[3]);
        }
    }
}

// ------------------------------------- fused layer1 aggregation + GEMM2 -----
__global__ void __launch_bounds__(256)
k_aggemm2(const float* __restrict__ b1, const float* __restrict__ W2, int n) {
    __shared__ float sW[HID * OUT_DIM];
    __shared__ float sA[32][129];
    int tid = threadIdx.x;
    int m0 = blockIdx.x * 32;
    int w = tid >> 5, lane = tid & 31;

    for (int i = tid; i < HID * OUT_DIM; i += 256) sW[i] = W2[i];

    const float4* h1 = (const float4*)g_h1;
    float4 bb = ((const float4*)b1)[lane];
    #pragma unroll 1
    for (int i = 0; i < 4; i++) {
        int r = w * 4 + i;
        int node = m0 + r;
        float4 acc = make_float4(0.f, 0.f, 0.f, 0.f);
        float sd = 0.f;
        if (node < n) {
            int beg = g_rowstart[node];
            int end = g_rowstart[node + 1];
            int j = beg;
            for (; j + 8 <= end; j += 8) {   // MLP=8
                int s0 = g_elist[j],     s1 = g_elist[j + 1];
                int s2 = g_elist[j + 2], s3 = g_elist[j + 3];
                int s4 = g_elist[j + 4], s5 = g_elist[j + 5];
                int s6 = g_elist[j + 6], s7 = g_elist[j + 7];
                float q0 = __ldg(&g_isd[s0]), q1 = __ldg(&g_isd[s1]);
                float q2 = __ldg(&g_isd[s2]), q3 = __ldg(&g_isd[s3]);
                float q4 = __ldg(&g_isd[s4]), q5 = __ldg(&g_isd[s5]);
                float q6 = __ldg(&g_isd[s6]), q7 = __ldg(&g_isd[s7]);
                float4 v0 = h1[(size_t)s0 * 32 + lane];
                float4 v1 = h1[(size_t)s1 * 32 + lane];
                float4 v2 = h1[(size_t)s2 * 32 + lane];
                float4 v3 = h1[(size_t)s3 * 32 + lane];
                float4 v4 = h1[(size_t)s4 * 32 + lane];
                float4 v5 = h1[(size_t)s5 * 32 + lane];
                float4 v6 = h1[(size_t)s6 * 32 + lane];
                float4 v7 = h1[(size_t)s7 * 32 + lane];
                acc.x += q0*v0.x + q1*v1.x + q2*v2.x + q3*v3.x
                       + q4*v4.x + q5*v5.x + q6*v6.x + q7*v7.x;
                acc.y += q0*v0.y + q1*v1.y + q2*v2.y + q3*v3.y
                       + q4*v4.y + q5*v5.y + q6*v6.y + q7*v7.y;
                acc.z += q0*v0.z + q1*v1.z + q2*v2.z + q3*v3.z
                       + q4*v4.z + q5*v5.z + q6*v6.z + q7*v7.z;
                acc.w += q0*v0.w + q1*v1.w + q2*v2.w + q3*v3.w
                       + q4*v4.w + q5*v5.w + q6*v6.w + q7*v7.w;
            }
            for (; j < end; j++) {
                int s = g_elist[j];
                float q = __ldg(&g_isd[s]);
                float4 v = h1[(size_t)s * 32 + lane];
                acc.x += q * v.x; acc.y += q * v.y;
                acc.z += q * v.z; acc.w += q * v.w;
            }
            sd = g_isd[node];
        }
        sA[r][lane * 4 + 0] = fmaxf(fmaf(sd, acc.x, bb.x), 0.f);
        sA[r][lane * 4 + 1] = fmaxf(fmaf(sd, acc.y, bb.y), 0.f);
        sA[r][lane * 4 + 2] = fmaxf(fmaf(sd, acc.z, bb.z), 0.f);
        sA[r][lane * 4 + 3] = fmaxf(fmaf(sd, acc.w, bb.w), 0.f);
    }
    __syncthreads();

    int m = tid & 31, g = tid >> 5;
    float acc2[5] = {};
    #pragma unroll 8
    for (int k = 0; k < HID; k++) {
        float a = sA[m][k];
        #pragma unroll
        for (int j = 0; j < 5; j++)
            acc2[j] = fmaf(a, sW[k * OUT_DIM + g * 5 + j], acc2[j]);
    }
    int row = m0 + m;
    if (row < n) {
        float s = g_isd[row];
        #pragma unroll
        for (int j = 0; j < 5; j++)
            g_h2[(size_t)row * OUT_DIM + g * 5 + j] = acc2[j] * s;
    }
}

// -------------------------------------------------- layer2 CSR aggregation --
__global__ void k_agg2(const float* __restrict__ b2, float* __restrict__ out, int n) {
    int i = blockIdx.x * blockDim.x + threadIdx.x;
    if (i >= n * 10) return;
    int node = i / 10;
    int c = i - node * 10;
    int beg = g_rowstart[node];
    int end = g_rowstart[node + 1];
    const float4* h2 = (const float4*)g_h2;
    float4 acc = make_float4(0.f, 0.f, 0.f, 0.f);
    int j = beg;
    for (; j + 4 <= end; j += 4) {
        int s0 = g_elist[j], s1 = g_elist[j + 1];
        int s2 = g_elist[j + 2], s3 = g_elist[j + 3];
        float4 v0 = h2[(size_t)s0 * 10 + c];
        float4 v1 = h2[(size_t)s1 * 10 + c];
        float4 v2 = h2[(size_t)s2 * 10 + c];
        float4 v3 = h2[(size_t)s3 * 10 + c];
        acc.x += v0.x + v1.x + v2.x + v3.x;
        acc.y += v0.y + v1.y + v2.y + v3.y;
        acc.z += v0.z + v1.z + v2.z + v3.z;
        acc.w += v0.w + v1.w + v2.w + v3.w;
    }
    for (; j < end; j++) {
        int s = g_elist[j];
        float4 v = h2[(size_t)s * 10 + c];
        acc.x += v.x; acc.y += v.y; acc.z += v.z; acc.w += v.w;
    }
    float sd = g_isd[node];
    float4 bb = ((const float4*)b2)[c];
    ((float4*)out)[i] = make_float4(fmaf(sd, acc.x, bb.x), fmaf(sd, acc.y, bb.y),
                                    fmaf(sd, acc.z, bb.z), fmaf(sd, acc.w, bb.w));
}

// ---------------------------------------------------------------- launch ----
extern "C" void kernel_launch(void* const* d_in, const int* in_sizes, int n_in,
                              void* d_out, int out_size) {
    const float* x   = (const float*)d_in[0];
    const int*   src = (const int*)d_in[1];
    const int*   dst = (const int*)d_in[2];
    const float* W1  = (const float*)d_in[3];
    const float* b1  = (const float*)d_in[4];
    const float* W2  = (const float*)d_in[5];
    const float* b2  = (const float*)d_in[6];
    float* out = (float*)d_out;

    int n = in_sizes[0] / IN_DIM;
    int e = in_sizes[1];

    static cudaStream_t s_side = 0;
    static cudaEvent_t e_fork = 0, e_join = 0;
    if (!s_side) {
        cudaFuncSetAttribute(k_gemm1, cudaFuncAttributeMaxDynamicSharedMemorySize,
                             SMEM_G1);
        cudaStreamCreateWithFlags(&s_side, cudaStreamNonBlocking);
        cudaEventCreateWithFlags(&e_fork, cudaEventDisableTiming);
        cudaEventCreateWithFlags(&e_join, cudaEventDisableTiming);
    }

    // Submission order chosen so k_gemm1 is the 6th kernel (ncu -s 5 -c 1).
    k_splitW1<<<(HID * IN_DIM + 255) / 256, 256>>>(W1);             // 1 (main)

    cudaEventRecord(e_fork, 0);
    cudaStreamWaitEvent(s_side, e_fork, 0);
    k_zero_deg<<<(n + 255) / 256, 256, 0, s_side>>>(n);             // 2
    k_count<<<(e + 255) / 256, 256, 0, s_side>>>(dst, e);           // 3
    k_isd<<<(n + 255) / 256, 256, 0, s_side>>>(n);                  // 4
    k_scan1<<<NB_SCAN, SCAN_BS, 0, s_side>>>(n);                    // 5

    k_gemm1<<<(n + 63) / 64, 256, SMEM_G1>>>(x, n);                 // 6 (main)

    k_scan2<<<1, 32, 0, s_side>>>(n, e);                            // 7
    k_scan3<<<(n + 255) / 256, 256, 0, s_side>>>(n);                // 8
    k_scatter<<<(e + 255) / 256, 256, 0, s_side>>>(src, dst, e);    // 9
    cudaEventRecord(e_join, s_side);

    cudaStreamWaitEvent(0, e_join, 0);
    k_aggemm2<<<(n + 31) / 32, 256>>>(b1, W2, n);                   // 10
    k_agg2<<<(n * 10 + 255) / 256, 256>>>(b2, out, n);              // 11
}

// round 10
// speedup vs baseline: 2.3399x; 1.0656x over previous
#include <cuda_runtime.h>
#include <cuda_fp16.h>

#define N_NODES 100000
#define N_EDGES 1600000
#define IN_DIM  256
#define HID     128
#define OUT_DIM 40
#define SCAN_BS 1024
#define NB_SCAN ((N_NODES + SCAN_BS - 1) / SCAN_BS)

typedef unsigned long long u64;
typedef unsigned int u32;

// ---- scratch ----
__device__ float g_deg[N_NODES];
__device__ float g_isd[N_NODES];
__device__ __align__(16) __half g_h1[(size_t)N_NODES * HID];     // fp16 x@W1
__device__ __align__(16) __half g_h2[(size_t)N_NODES * OUT_DIM]; // fp16 layer2
__device__ __align__(16) __half g_W1h[HID * IN_DIM];             // fp16(W1), [n][k]
__device__ int g_rowstart[N_NODES + 1];
__device__ int g_cursor[N_NODES];
__device__ int g_bsum[NB_SCAN];
__device__ int g_elist[N_EDGES];

// ---------------------------------------------------------------- degree ----
__global__ void k_zero_deg(int n) {
    int i = blockIdx.x * blockDim.x + threadIdx.x;
    if (i < n) g_deg[i] = 0.f;
}
__global__ void k_count(const int* __restrict__ dst, int e) {
    int i = blockIdx.x * blockDim.x + threadIdx.x;
    if (i < e) atomicAdd(&g_deg[dst[i]], 1.0f);
}
__global__ void k_isd(int n) {
    int i = blockIdx.x * blockDim.x + threadIdx.x;
    if (i < n) {
        float d = g_deg[i];
        g_isd[i] = (d > 0.f) ? rsqrtf(d) : 0.f;
    }
}

// ----------------------------------------------------------- CSR build ------
__global__ void k_scan1(int n) {
    __shared__ int sm[SCAN_BS];
    int t = threadIdx.x;
    int idx = blockIdx.x * SCAN_BS + t;
    int v = (idx < n) ? (int)g_deg[idx] : 0;
    sm[t] = v;
    __syncthreads();
    #pragma unroll
    for (int off = 1; off < SCAN_BS; off <<= 1) {
        int y = (t >= off) ? sm[t - off] : 0;
        __syncthreads();
        sm[t] += y;
        __syncthreads();
    }
    if (idx < n) g_rowstart[idx] = sm[t] - v;
    if (t == SCAN_BS - 1) g_bsum[blockIdx.x] = sm[t];
}
__global__ void k_scan2(int n, int e) {
    if (threadIdx.x == 0) {
        int run = 0;
        for (int i = 0; i < NB_SCAN; i++) {
            int t = g_bsum[i];
            g_bsum[i] = run;
            run += t;
        }
        g_rowstart[n] = run;
    }
}
__global__ void k_scan3(int n) {
    int i = blockIdx.x * blockDim.x + threadIdx.x;
    if (i < n) {
        int rs = g_rowstart[i] + g_bsum[i >> 10];
        g_rowstart[i] = rs;
        g_cursor[i] = rs;
    }
}
__global__ void k_scatter(const int* __restrict__ src, const int* __restrict__ dst, int e) {
    int i = blockIdx.x * blockDim.x + threadIdx.x;
    if (i < e) {
        int pos = atomicAdd(&g_cursor[dst[i]], 1);
        g_elist[pos] = src[i];
    }
}

// --------------------------------------------------- W1 -> fp16 [n][k] ------
__global__ void k_splitW1(const float* __restrict__ W1) {
    int i = blockIdx.x * blockDim.x + threadIdx.x;
    if (i >= HID * IN_DIM) return;
    int n = i & (HID - 1), k = i >> 7;
    g_W1h[n * IN_DIM + k] = __float2half(W1[(size_t)k * HID + n]);
}

// -------------------------------------------------------------- HMMA GEMM1 --
// h1 = x @ W1 via 2-pass fp16 split (Markidis). Output stored fp16.
#define A_HI   0
#define A_LO   8192
#define B_H    16384
#define AB_STRIDE 32768
#define SMEM_G1 (2 * AB_STRIDE)   // 64 KB

__device__ __forceinline__ u32 toff(int r, int cb) {
    return (u32)((r >> 3) * 1024 + (r & 7) * 128 + (cb ^ ((r & 7) << 4)));
}
__device__ __forceinline__ void ldsm4(u32* r, u32 addr) {
    asm volatile("ldmatrix.sync.aligned.m8n8.x4.shared.b16 {%0,%1,%2,%3}, [%4];"
                 : "=r"(r[0]), "=r"(r[1]), "=r"(r[2]), "=r"(r[3]) : "r"(addr));
}
__device__ __forceinline__ void mma16816(float* c, const u32* a, const u32* b) {
    asm volatile(
        "mma.sync.aligned.m16n8k16.row.col.f32.f16.f16.f32 "
        "{%0,%1,%2,%3}, {%4,%5,%6,%7}, {%8,%9}, {%0,%1,%2,%3};"
        : "+f"(c[0]), "+f"(c[1]), "+f"(c[2]), "+f"(c[3])
        : "r"(a[0]), "r"(a[1]), "r"(a[2]), "r"(a[3]), "r"(b[0]), "r"(b[1]));
}

__global__ void __launch_bounds__(256, 2)
k_gemm1(const float* __restrict__ x, int n) {
    extern __shared__ char smem[];
    u32 sb;
    asm("{ .reg .u64 t; cvta.to.shared.u64 t, %1; cvt.u32.u64 %0, t; }"
        : "=r"(sb) : "l"(smem));
    const int tid = threadIdx.x;
    const int l = tid & 31;
    const int wid = tid >> 5;
    const int wm = wid & 1;
    const int wn = wid >> 1;
    const int m0 = blockIdx.x * 64;

    float4 ra[4];
    uint4 rbh[4];

    #pragma unroll
    for (int j = 0; j < 4; j++) {
        int u = tid + j * 256;
        int r = u >> 4, kq = (u & 15) * 4;
        int row = m0 + r;
        ra[j] = (row < n) ? *(const float4*)&x[(size_t)row * IN_DIM + kq]
                          : make_float4(0.f, 0.f, 0.f, 0.f);
    }
    #pragma unroll
    for (int j = 0; j < 4; j++) {
        int u = tid + j * 256;
        int r = u >> 3, kq = (u & 7) * 8;
        rbh[j] = *(const uint4*)&g_W1h[r * IN_DIM + kq];
    }

    #pragma unroll
    for (int j = 0; j < 4; j++) {
        int u = tid + j * 256;
        int r = u >> 4, kq = (u & 15) * 4;
        float4 v = ra[j];
        __half h0 = __float2half(v.x), h1h = __float2half(v.y);
        __half h2 = __float2half(v.z), h3 = __float2half(v.w);
        __half l0 = __float2half(v.x - __half2float(h0));
        __half l1 = __float2half(v.y - __half2float(h1h));
        __half l2 = __float2half(v.z - __half2float(h2));
        __half l3 = __float2half(v.w - __half2float(h3));
        u32 off = toff(r, kq * 2);
        __half2 ph0 = __halves2half2(h0, h1h), ph1 = __halves2half2(h2, h3);
        __half2 pl0 = __halves2half2(l0, l1), pl1 = __halves2half2(l2, l3);
        *(uint2*)(smem + A_HI + off) = make_uint2(*(u32*)&ph0, *(u32*)&ph1);
        *(uint2*)(smem + A_LO + off) = make_uint2(*(u32*)&pl0, *(u32*)&pl1);
    }
    #pragma unroll
    for (int j = 0; j < 4; j++) {
        int u = tid + j * 256;
        int r = u >> 3, kq = (u & 7) * 8;
        *(uint4*)(smem + B_H + toff(r, kq * 2)) = rbh[j];
    }
    __syncthreads();

    float acc[2][4][4] = {};

    u32 PA[2], XA[2];
    #pragma unroll
    for (int mb = 0; mb < 2; mb++) {
        int r = wm * 32 + mb * 16 + (l & 7) + 8 * ((l >> 3) & 1);
        PA[mb] = (u32)((r >> 3) * 1024 + (r & 7) * 128);
        XA[mb] = (u32)((r & 7) << 4);
    }
    u32 cblA = 16 * (l >> 4);
    u32 PB[2], XB[2];
    #pragma unroll
    for (int nb = 0; nb < 2; nb++) {
        int r = wn * 32 + nb * 16 + (l & 7) + 8 * ((l >> 4) & 1);
        PB[nb] = (u32)((r >> 3) * 1024 + (r & 7) * 128);
        XB[nb] = (u32)((r & 7) << 4);
    }
    u32 cblB = 16 * ((l >> 3) & 1);

    #pragma unroll 1
    for (int ch = 0; ch < 4; ch++) {
        u32 base = sb + (u32)(ch & 1) * AB_STRIDE;

        if (ch < 3) {
            int k0 = (ch + 1) * 64;
            #pragma unroll
            for (int j = 0; j < 4; j++) {
                int u = tid + j * 256;
                int r = u >> 4, kq = (u & 15) * 4;
                int row = m0 + r;
                ra[j] = (row < n) ? *(const float4*)&x[(size_t)row * IN_DIM + k0 + kq]
                                  : make_float4(0.f, 0.f, 0.f, 0.f);
            }
            #pragma unroll
            for (int j = 0; j < 4; j++) {
                int u = tid + j * 256;
                int r = u >> 3, kq = (u & 7) * 8;
                rbh[j] = *(const uint4*)&g_W1h[r * IN_DIM + k0 + kq];
            }
        }

        #pragma unroll
        for (int ks = 0; ks < 4; ks++) {
            u32 kb = ks * 32;
            u32 Ah[2][4], Al[2][4], Bh[2][4];
            #pragma unroll
            for (int mb = 0; mb < 2; mb++) {
                u32 aoff = PA[mb] + ((kb + cblA) ^ XA[mb]);
                ldsm4(Ah[mb], base + A_HI + aoff);
                ldsm4(Al[mb], base + A_LO + aoff);
            }
            #pragma unroll
            for (int nb = 0; nb < 2; nb++) {
                u32 boff = PB[nb] + ((kb + cblB) ^ XB[nb]);
                ldsm4(Bh[nb], base + B_H + boff);
            }
            #pragma unroll
            for (int mb = 0; mb < 2; mb++)
                #pragma unroll
                for (int nb = 0; nb < 2; nb++)
                    #pragma unroll
                    for (int j = 0; j < 2; j++) {
                        float* c = acc[mb][nb * 2 + j];
                        mma16816(c, Ah[mb], &Bh[nb][2 * j]);
                        mma16816(c, Al[mb], &Bh[nb][2 * j]);
                    }
        }

        if (ch < 3) {
            char* nb_ = smem + ((ch + 1) & 1) * AB_STRIDE;
            #pragma unroll
            for (int j = 0; j < 4; j++) {
                int u = tid + j * 256;
                int r = u >> 4, kq = (u & 15) * 4;
                float4 v = ra[j];
                __half h0 = __float2half(v.x), h1h = __float2half(v.y);
                __half h2 = __float2half(v.z), h3 = __float2half(v.w);
                __half l0 = __float2half(v.x - __half2float(h0));
                __half l1 = __float2half(v.y - __half2float(h1h));
                __half l2 = __float2half(v.z - __half2float(h2));
                __half l3 = __float2half(v.w - __half2float(h3));
                u32 off = toff(r, kq * 2);
                __half2 ph0 = __halves2half2(h0, h1h), ph1 = __halves2half2(h2, h3);
                __half2 pl0 = __halves2half2(l0, l1), pl1 = __halves2half2(l2, l3);
                *(uint2*)(nb_ + A_HI + off) = make_uint2(*(u32*)&ph0, *(u32*)&ph1);
                *(uint2*)(nb_ + A_LO + off) = make_uint2(*(u32*)&pl0, *(u32*)&pl1);
            }
            #pragma unroll
            for (int j = 0; j < 4; j++) {
                int u = tid + j * 256;
                int r = u >> 3, kq = (u & 7) * 8;
                *(uint4*)(nb_ + B_H + toff(r, kq * 2)) = rbh[j];
            }
            __syncthreads();
        }
    }

    // epilogue: store h1 as fp16
    #pragma unroll
    for (int mb = 0; mb < 2; mb++) {
        int r0 = m0 + wm * 32 + mb * 16 + (l >> 2);
        int r1 = r0 + 8;
        #pragma unroll
        for (int idx = 0; idx < 4; idx++) {
            int col = wn * 32 + idx * 8 + (l & 3) * 2;
            float* c = acc[mb][idx];
            if (r0 < n) {
                __half2 p = __floats2half2_rn(c[0], c[1]);
                *(u32*)&g_h1[(size_t)r0 * HID + col] = *(u32*)&p;
            }
            if (r1 < n) {
                __half2 p = __floats2half2_rn(c[2], c[3]);
                *(u32*)&g_h1[(size_t)r1 * HID + col] = *(u32*)&p;
            }
        }
    }
}

// ------------------------------------- fused layer1 aggregation + GEMM2 -----
// gather fp16 h1 (uint2 = 4 halves per lane), fp32 accumulate.
__global__ void __launch_bounds__(256)
k_aggemm2(const float* __restrict__ b1, const float* __restrict__ W2, int n) {
    __shared__ float sW[HID * OUT_DIM];
    __shared__ float sA[32][129];
    int tid = threadIdx.x;
    int m0 = blockIdx.x * 32;
    int w = tid >> 5, lane = tid & 31;

    for (int i = tid; i < HID * OUT_DIM; i += 256) sW[i] = W2[i];

    const uint2* h1 = (const uint2*)g_h1;   // 4 halves per uint2, 32 per row
    float4 bb = ((const float4*)b1)[lane];
    #pragma unroll 1
    for (int i = 0; i < 4; i++) {
        int r = w * 4 + i;
        int node = m0 + r;
        float4 acc = make_float4(0.f, 0.f, 0.f, 0.f);
        float sd = 0.f;
        if (node < n) {
            int beg = g_rowstart[node];
            int end = g_rowstart[node + 1];
            int j = beg;
            for (; j + 8 <= end; j += 8) {
                int s0 = g_elist[j],     s1 = g_elist[j + 1];
                int s2 = g_elist[j + 2], s3 = g_elist[j + 3];
                int s4 = g_elist[j + 4], s5 = g_elist[j + 5];
                int s6 = g_elist[j + 6], s7 = g_elist[j + 7];
                float q0 = __ldg(&g_isd[s0]), q1 = __ldg(&g_isd[s1]);
                float q2 = __ldg(&g_isd[s2]), q3 = __ldg(&g_isd[s3]);
                float q4 = __ldg(&g_isd[s4]), q5 = __ldg(&g_isd[s5]);
                float q6 = __ldg(&g_isd[s6]), q7 = __ldg(&g_isd[s7]);
                uint2 u0 = h1[(size_t)s0 * 32 + lane];
                uint2 u1 = h1[(size_t)s1 * 32 + lane];
                uint2 u2 = h1[(size_t)s2 * 32 + lane];
                uint2 u3 = h1[(size_t)s3 * 32 + lane];
                uint2 u4 = h1[(size_t)s4 * 32 + lane];
                uint2 u5 = h1[(size_t)s5 * 32 + lane];
                uint2 u6 = h1[(size_t)s6 * 32 + lane];
                uint2 u7 = h1[(size_t)s7 * 32 + lane];
                #define ACC_EDGE(uu, qq) { \
                    float2 a0 = __half22float2(*(__half2*)&uu.x); \
                    float2 a1 = __half22float2(*(__half2*)&uu.y); \
                    acc.x = fmaf(qq, a0.x, acc.x); acc.y = fmaf(qq, a0.y, acc.y); \
                    acc.z = fmaf(qq, a1.x, acc.z); acc.w = fmaf(qq, a1.y, acc.w); }
                ACC_EDGE(u0, q0) ACC_EDGE(u1, q1) ACC_EDGE(u2, q2) ACC_EDGE(u3, q3)
                ACC_EDGE(u4, q4) ACC_EDGE(u5, q5) ACC_EDGE(u6, q6) ACC_EDGE(u7, q7)
            }
            for (; j < end; j++) {
                int s = g_elist[j];
                float q = __ldg(&g_isd[s]);
                uint2 uu = h1[(size_t)s * 32 + lane];
                ACC_EDGE(uu, q)
                #undef ACC_EDGE
            }
            sd = g_isd[node];
        }
        sA[r][lane * 4 + 0] = fmaxf(fmaf(sd, acc.x, bb.x), 0.f);
        sA[r][lane * 4 + 1] = fmaxf(fmaf(sd, acc.y, bb.y), 0.f);
        sA[r][lane * 4 + 2] = fmaxf(fmaf(sd, acc.z, bb.z), 0.f);
        sA[r][lane * 4 + 3] = fmaxf(fmaf(sd, acc.w, bb.w), 0.f);
    }
    __syncthreads();

    int m = tid & 31, g = tid >> 5;
    float acc2[5] = {};
    #pragma unroll 8
    for (int k = 0; k < HID; k++) {
        float a = sA[m][k];
        #pragma unroll
        for (int j = 0; j < 5; j++)
            acc2[j] = fmaf(a, sW[k * OUT_DIM + g * 5 + j], acc2[j]);
    }
    int row = m0 + m;
    if (row < n) {
        float s = g_isd[row];
        #pragma unroll
        for (int j = 0; j < 5; j++)
            g_h2[(size_t)row * OUT_DIM + g * 5 + j] = __float2half(acc2[j] * s);
    }
}

// -------------------------------------------------- layer2 CSR aggregation --
// thread per (node, 4-half chunk c<10); gathers fp16 h2, fp32 accumulate.
__global__ void k_agg2(const float* __restrict__ b2, float* __restrict__ out, int n) {
    int i = blockIdx.x * blockDim.x + threadIdx.x;
    if (i >= n * 10) return;
    int node = i / 10;
    int c = i - node * 10;
    int beg = g_rowstart[node];
    int end = g_rowstart[node + 1];
    const uint2* h2 = (const uint2*)g_h2;   // 4 halves per uint2, 10 per row
    float4 acc = make_float4(0.f, 0.f, 0.f, 0.f);
    int j = beg;
    #define ACC2(uu) { \
        float2 a0 = __half22float2(*(__half2*)&uu.x); \
        float2 a1 = __half22float2(*(__half2*)&uu.y); \
        acc.x += a0.x; acc.y += a0.y; acc.z += a1.x; acc.w += a1.y; }
    for (; j + 4 <= end; j += 4) {
        int s0 = g_elist[j], s1 = g_elist[j + 1];
        int s2 = g_elist[j + 2], s3 = g_elist[j + 3];
        uint2 u0 = h2[(size_t)s0 * 10 + c];
        uint2 u1 = h2[(size_t)s1 * 10 + c];
        uint2 u2 = h2[(size_t)s2 * 10 + c];
        uint2 u3 = h2[(size_t)s3 * 10 + c];
        ACC2(u0) ACC2(u1) ACC2(u2) ACC2(u3)
    }
    for (; j < end; j++) {
        int s = g_elist[j];
        uint2 uu = h2[(size_t)s * 10 + c];
        ACC2(uu)
    }
    #undef ACC2
    float sd = g_isd[node];
    float4 bb = ((const float4*)b2)[c];
    ((float4*)out)[i] = make_float4(fmaf(sd, acc.x, bb.x), fmaf(sd, acc.y, bb.y),
                                    fmaf(sd, acc.z, bb.z), fmaf(sd, acc.w, bb.w));
}

// ---------------------------------------------------------------- launch ----
extern "C" void kernel_launch(void* const* d_in, const int* in_sizes, int n_in,
                              void* d_out, int out_size) {
    const float* x   = (const float*)d_in[0];
    const int*   src = (const int*)d_in[1];
    const int*   dst = (const int*)d_in[2];
    const float* W1  = (const float*)d_in[3];
    const float* b1  = (const float*)d_in[4];
    const float* W2  = (const float*)d_in[5];
    const float* b2  = (const float*)d_in[6];
    float* out = (float*)d_out;

    int n = in_sizes[0] / IN_DIM;
    int e = in_sizes[1];

    static cudaStream_t s_side = 0;
    static cudaEvent_t e_fork = 0, e_join = 0;
    if (!s_side) {
        cudaFuncSetAttribute(k_gemm1, cudaFuncAttributeMaxDynamicSharedMemorySize,
                             SMEM_G1);
        cudaStreamCreateWithFlags(&s_side, cudaStreamNonBlocking);
        cudaEventCreateWithFlags(&e_fork, cudaEventDisableTiming);
        cudaEventCreateWithFlags(&e_join, cudaEventDisableTiming);
    }

    k_splitW1<<<(HID * IN_DIM + 255) / 256, 256>>>(W1);             // 1 (main)

    cudaEventRecord(e_fork, 0);
    cudaStreamWaitEvent(s_side, e_fork, 0);
    k_zero_deg<<<(n + 255) / 256, 256, 0, s_side>>>(n);             // 2
    k_count<<<(e + 255) / 256, 256, 0, s_side>>>(dst, e);           // 3
    k_isd<<<(n + 255) / 256, 256, 0, s_side>>>(n);                  // 4
    k_scan1<<<NB_SCAN, SCAN_BS, 0, s_side>>>(n);                    // 5

    k_gemm1<<<(n + 63) / 64, 256, SMEM_G1>>>(x, n);                 // 6 (main)

    k_scan2<<<1, 32, 0, s_side>>>(n, e);                            // 7
    k_scan3<<<(n + 255) / 256, 256, 0, s_side>>>(n);                // 8
    k_scatter<<<(e + 255) / 256, 256, 0, s_side>>>(src, dst, e);    // 9
    cudaEventRecord(e_join, s_side);

    cudaStreamWaitEvent(0, e_join, 0);
    k_aggemm2<<<(n + 31) / 32, 256>>>(b1, W2, n);                   // 10
    k_agg2<<<(n * 10 + 255) / 256, 256>>>(b2, out, n);              // 11
}